// round 7
// baseline (speedup 1.0000x reference)
#include <cuda_runtime.h>

#define NN 50000
#define EE 800000
#define SP 136
#define NTILE_E (EE / 128)
#define NTILE_N ((NN + 127) / 128)
#define PGRID 148

// ---------------- scratch (device globals) ----------------------------------
__device__ int   g_is64;
__device__ int   g_src[EE];
__device__ int   g_dst[EE];
__device__ float g_A[NN * 128];    // h @ We1[0:128]
__device__ float g_B[NN * 128];    // h @ We1[128:256]
__device__ float g_agg[NN * 128];  // segment-sum of m

__device__ __forceinline__ float siluf(float v) {
    float t;
    asm("tanh.approx.f32 %0, %1;" : "=f"(t) : "f"(0.5f * v));
    return 0.5f * v * (1.0f + t);
}

__device__ __forceinline__ unsigned f2tf(float v) {
    unsigned u;
    asm("cvt.rna.tf32.f32 %0, %1;" : "=r"(u) : "f"(v));
    return u;
}

// permuted slot of k within its 8-group: pairs (t, t+4) adjacent
__device__ __forceinline__ int kpos(int k) {
    return (k & ~7) + ((k & 3) * 2 + ((k >> 2) & 1));
}

__device__ __forceinline__ void mma8(float* c, const unsigned* a, const unsigned* b) {
    asm volatile(
        "mma.sync.aligned.m16n8k8.row.col.f32.tf32.tf32.f32 "
        "{%0,%1,%2,%3},{%4,%5,%6,%7},{%8,%9},{%0,%1,%2,%3};"
        : "+f"(c[0]), "+f"(c[1]), "+f"(c[2]), "+f"(c[3])
        : "r"(a[0]), "r"(a[1]), "r"(a[2]), "r"(a[3]), "r"(b[0]), "r"(b[1]));
}

// ---- stage weight 128x128 row-major -> WT[n][kpos(k)] tf32 (1024 thr) ------
__device__ __forceinline__ void stage_wtp(float* wt, const float* __restrict__ W,
                                          int tid) {
#pragma unroll
    for (int s = 0; s < 16; s++) {
        int i = s * 1024 + tid;
        int n = i & 127, k = i >> 7;
        wt[n * SP + kpos(k)] = __uint_as_float(f2tf(W[k * 128 + n]));
    }
}

// non-permuted staging (for fp32-A pass)
__device__ __forceinline__ void stage_wtn(float* wt, const float* __restrict__ W,
                                          int tid) {
#pragma unroll
    for (int s = 0; s < 16; s++) {
        int i = s * 1024 + tid;
        int n = i & 127, k = i >> 7;
        wt[n * SP + k] = __uint_as_float(f2tf(W[k * 128 + n]));
    }
}

// ---- permuted-tf32 k-loop: M=16, N=32, K=128 -------------------------------
__device__ __forceinline__ void gemm_kloop16p(const float* sA, const float* wt,
                                              int mrow, int ncol, int lane,
                                              float acc[4][4]) {
    int g = lane >> 2, tg = lane & 3;
    const float* ap0 = sA + (mrow + g) * SP + 2 * tg;
    const float* ap1 = ap0 + 8 * SP;
    const float* bp0 = wt + (ncol + g) * SP + 2 * tg;
#pragma unroll
    for (int kk = 0; kk < 16; kk++) {
        int k0 = kk * 8;
        float2 a02 = *(const float2*)(ap0 + k0);
        float2 a13 = *(const float2*)(ap1 + k0);
        unsigned a[4] = {__float_as_uint(a02.x), __float_as_uint(a13.x),
                         __float_as_uint(a02.y), __float_as_uint(a13.y)};
#pragma unroll
        for (int nt = 0; nt < 4; nt++) {
            float2 b = *(const float2*)(bp0 + nt * 8 * SP + k0);
            unsigned bb[2] = {__float_as_uint(b.x), __float_as_uint(b.y)};
            mma8(acc[nt], a, bb);
        }
    }
}

// ---- fp32-A non-perm k-loop: M=16, N=32, K=128 (A cvt on load) -------------
__device__ __forceinline__ void gemm_kloop16n(const float* sA, const float* wt,
                                              int mrow, int ncol, int lane,
                                              float acc[4][4]) {
    int g = lane >> 2, tg = lane & 3;
    const float* a0p = sA + (mrow + g) * SP + tg;
    const float* b0p = wt + (ncol + g) * SP + tg;
#pragma unroll
    for (int kk = 0; kk < 16; kk++) {
        int k0 = kk * 8;
        unsigned a[4];
        a[0] = f2tf(a0p[k0]);
        a[1] = f2tf(a0p[8 * SP + k0]);
        a[2] = f2tf(a0p[k0 + 4]);
        a[3] = f2tf(a0p[8 * SP + k0 + 4]);
#pragma unroll
        for (int nt = 0; nt < 4; nt++) {
            const float* bp = b0p + nt * 8 * SP + k0;
            unsigned b[2] = {__float_as_uint(bp[0]), __float_as_uint(bp[4])};
            mma8(acc[nt], a, b);
        }
    }
}

// ---------------- index dtype detection + conversion ------------------------
__global__ void k_detect(const void* ei) {
    if (blockIdx.x == 0 && threadIdx.x == 0) {
        const int* p = (const int*)ei;
        int acc = 0;
        for (int i = 0; i < 64; i++) acc |= p[2 * i + 1];
        g_is64 = (acc == 0) ? 1 : 0;
    }
}

__global__ void k_convert(const void* ei) {
    int e = blockIdx.x * blockDim.x + threadIdx.x;
    if (e >= EE) return;
    if (g_is64) {
        const long long* p = (const long long*)ei;
        g_src[e] = (int)p[e];
        g_dst[e] = (int)p[EE + e];
    } else {
        const int* p = (const int*)ei;
        g_src[e] = p[e];
        g_dst[e] = p[EE + e];
    }
}

// ---------------- init: zero agg, x_out = x ---------------------------------
__global__ void k_init(const float* __restrict__ x, float* __restrict__ outx) {
    for (int i = blockIdx.x * blockDim.x + threadIdx.x; i < NN * 128;
         i += gridDim.x * blockDim.x) {
        g_agg[i] = 0.0f;
        if (i < NN * 3) outx[i] = x[i];
    }
}

// ---------------- node pre-GEMM (persistent, 1024 thr) ----------------------
__global__ __launch_bounds__(1024, 1) void k_node_pre(
    const float* __restrict__ h, const float* __restrict__ We1) {
    extern __shared__ float sm[];
    float* ht = sm;               // 128*SP perm tf32
    float* wtA = ht + 128 * SP;
    float* wtB = wtA + 128 * SP;

    int tid = threadIdx.x, lane = tid & 31, warp = tid >> 5;
    stage_wtp(wtA, We1, tid);
    stage_wtp(wtB, We1 + 128 * 128, tid);
    __syncthreads();

    int mrow = (warp >> 2) * 16, ncol = (warp & 3) * 32;
    int g = lane >> 2, tg = lane & 3;

    for (int t = blockIdx.x; t < NTILE_N; t += gridDim.x) {
        int n0 = t * 128;
#pragma unroll
        for (int v = 0; v < 4; v++) {
            int f = v * 1024 + tid;
            int r = f >> 5, c4 = (f & 31) * 4;
            float4 val = make_float4(0.f, 0.f, 0.f, 0.f);
            if (n0 + r < NN) val = *(const float4*)&h[(n0 + r) * 128 + c4];
            int base = r * SP + (c4 & ~7);
            int off = (c4 & 7) >> 2;
            ht[base + 0 + off] = __uint_as_float(f2tf(val.x));
            ht[base + 2 + off] = __uint_as_float(f2tf(val.y));
            ht[base + 4 + off] = __uint_as_float(f2tf(val.z));
            ht[base + 6 + off] = __uint_as_float(f2tf(val.w));
        }
        __syncthreads();
#pragma unroll
        for (int half = 0; half < 2; half++) {
            float acc[4][4];
#pragma unroll
            for (int nt = 0; nt < 4; nt++)
#pragma unroll
                for (int l = 0; l < 4; l++) acc[nt][l] = 0.f;
            gemm_kloop16p(ht, half ? wtB : wtA, mrow, ncol, lane, acc);
            float* out = half ? g_B : g_A;
#pragma unroll
            for (int nt = 0; nt < 4; nt++) {
                int r = mrow + g;
                int cb = ncol + nt * 8 + tg * 2;
                if (n0 + r < NN)
                    *(float2*)&out[(n0 + r) * 128 + cb] = make_float2(acc[nt][0], acc[nt][1]);
                if (n0 + r + 8 < NN)
                    *(float2*)&out[(n0 + r + 8) * 128 + cb] = make_float2(acc[nt][2], acc[nt][3]);
            }
        }
        __syncthreads();
    }
}

// ---------------- fused edge kernel (persistent, 1024 thr) ------------------
__global__ __launch_bounds__(1024, 1) void k_edge(
    const float* __restrict__ x, const float* __restrict__ ea,
    const float* __restrict__ We1, const float* __restrict__ be1,
    const float* __restrict__ We2, const float* __restrict__ be2,
    const float* __restrict__ Wx1, const float* __restrict__ bx1,
    const float* __restrict__ Wx2, const float* __restrict__ bx2,
    float* __restrict__ outx) {
    extern __shared__ float sm[];
    float* tile = sm;                   // 128*SP (pre -> s -> mm)
    float* wt2 = tile + 128 * SP;       // We2^T perm
    float* wtx = wt2 + 128 * SP;        // Wx1^T perm
    float* sEA = wtx + 128 * SP;        // 128*20: ea[16]|dist|si|di|pad
    float* wtE = sEA + 128 * 20;        // 128*16: edge-attr weight block, perm
    float* wds = wtE + 128 * 16;
    float* be1s = wds + 128;
    float* be2s = be1s + 128;
    float* bx1s = be2s + 128;
    float* wx2s = bx1s + 128;
    float* sgate = wx2s + 128;

    int tid = threadIdx.x, lane = tid & 31, warp = tid >> 5;

    // ---- one-time staging ----
    stage_wtp(wt2, We2, tid);
    stage_wtp(wtx, Wx1, tid);
#pragma unroll
    for (int s = 0; s < 2; s++) {
        int i = s * 1024 + tid;
        int n = i & 127, k = i >> 7;
        wtE[n * 16 + kpos(k)] = __uint_as_float(f2tf(We1[(256 + k) * 128 + n]));
    }
    if (tid < 128) {
        wds[tid] = We1[272 * 128 + tid];
        be1s[tid] = be1[tid];
        be2s[tid] = be2[tid];
        bx1s[tid] = bx1[tid];
        wx2s[tid] = Wx2[tid];
    }
    float bx2v = bx2[0];
    __syncthreads();

    int mrow = (warp >> 2) * 16, ncol = (warp & 3) * 32;
    int g = lane >> 2, tg = lane & 3;
    int e_l = tid >> 3, q = tid & 7;

    for (int t = blockIdx.x; t < NTILE_E; t += gridDim.x) {
        int e0 = t * 128;

        // ---- stage edge tile ----
        {
            int e = e0 + e_l;
            *(float2*)&sEA[e_l * 20 + q * 2] = *(const float2*)&ea[e * 16 + q * 2];
            if (q == 0) {
                int si = g_src[e], di = g_dst[e];
                float dx = x[di * 3 + 0] - x[si * 3 + 0];
                float dy = x[di * 3 + 1] - x[si * 3 + 1];
                float dz = x[di * 3 + 2] - x[si * 3 + 2];
                sEA[e_l * 20 + 16] = sqrtf(dx * dx + dy * dy + dz * dz + 1e-9f);
                ((int*)sEA)[e_l * 20 + 17] = si;
                ((int*)sEA)[e_l * 20 + 18] = di;
            }
            if (tid < 128) sgate[tid] = bx2v;
        }
        __syncthreads();

        // ---- ea-GEMM (K=16): pre = ea @ We1e -> tile (perm slots, raw fp32) -
        {
            float acc[4][4];
#pragma unroll
            for (int nt = 0; nt < 4; nt++)
#pragma unroll
                for (int l = 0; l < 4; l++) acc[nt][l] = 0.f;
            const float* a0p = sEA + (mrow + g) * 20 + tg;
            const float* b0p = wtE + (ncol + g) * 16 + 2 * tg;
#pragma unroll
            for (int kk = 0; kk < 2; kk++) {
                int k0 = kk * 8;
                unsigned a[4];
                a[0] = f2tf(a0p[k0]);
                a[1] = f2tf(a0p[8 * 20 + k0]);
                a[2] = f2tf(a0p[k0 + 4]);
                a[3] = f2tf(a0p[8 * 20 + k0 + 4]);
#pragma unroll
                for (int nt = 0; nt < 4; nt++) {
                    float2 b = *(const float2*)(b0p + nt * 8 * 16 + k0);
                    unsigned bb[2] = {__float_as_uint(b.x), __float_as_uint(b.y)};
                    mma8(acc[nt], a, bb);
                }
            }
#pragma unroll
            for (int rr = 0; rr < 2; rr++) {
                int row = mrow + g + rr * 8;
#pragma unroll
                for (int nt = 0; nt < 4; nt++) {
                    int c = ncol + nt * 8 + tg * 2;
                    int base = row * SP + (c & ~7);
                    int j = c & 7;
                    tile[base + (j & 3) * 2 + (j >> 2)] = acc[nt][rr * 2 + 0];
                    tile[base + ((j + 1) & 3) * 2 + ((j + 1) >> 2)] = acc[nt][rr * 2 + 1];
                }
            }
        }
        __syncthreads();

        // ---- phase B (row-coalesced): s = silu(pre + A[src]+B[dst]+dist*wd+be1)
        {
            int row = e_l;                 // one row per thread, cols q*16..q*16+15
            float dist = sEA[row * 20 + 16];
            int si = ((const int*)sEA)[row * 20 + 17];
            int di = ((const int*)sEA)[row * 20 + 18];
            const float* Ar = &g_A[si * 128 + q * 16];
            const float* Br = &g_B[di * 128 + q * 16];
            float av[16], bv[16];
#pragma unroll
            for (int b4 = 0; b4 < 4; b4++) {
                float4 a4 = *(const float4*)&Ar[b4 * 4];
                float4 b4v = *(const float4*)&Br[b4 * 4];
                av[b4 * 4 + 0] = a4.x; av[b4 * 4 + 1] = a4.y;
                av[b4 * 4 + 2] = a4.z; av[b4 * 4 + 3] = a4.w;
                bv[b4 * 4 + 0] = b4v.x; bv[b4 * 4 + 1] = b4v.y;
                bv[b4 * 4 + 2] = b4v.z; bv[b4 * 4 + 3] = b4v.w;
            }
            float* tp = &tile[row * SP + q * 16];
#pragma unroll
            for (int grp = 0; grp < 2; grp++) {
                int gb = grp * 8;
                int c0 = q * 16 + gb;
#pragma unroll
                for (int tt = 0; tt < 4; tt++) {
                    float2 pre = *(float2*)&tp[gb + 2 * tt];
                    int ca = gb + tt, cb2 = gb + tt + 4;
                    float v0 = pre.x + av[ca] + bv[ca] + dist * wds[c0 + tt] + be1s[c0 + tt];
                    float v1 = pre.y + av[cb2] + bv[cb2] + dist * wds[c0 + tt + 4] +
                               be1s[c0 + tt + 4];
                    *(float2*)&tp[gb + 2 * tt] =
                        make_float2(__uint_as_float(f2tf(siluf(v0))),
                                    __uint_as_float(f2tf(siluf(v1))));
                }
            }
        }
        __syncthreads();

        // ---- GEMM1: mm = s @ We2 + be2 ----
        float accm[4][4];
#pragma unroll
        for (int nt = 0; nt < 4; nt++) {
            int cb = ncol + nt * 8 + tg * 2;
            float b0v = be2s[cb], b1v = be2s[cb + 1];
            accm[nt][0] = b0v; accm[nt][1] = b1v;
            accm[nt][2] = b0v; accm[nt][3] = b1v;
        }
        gemm_kloop16p(tile, wt2, mrow, ncol, lane, accm);

        // agg scatter straight from accumulators (fire-and-forget)
#pragma unroll
        for (int rr = 0; rr < 2; rr++) {
            int row = mrow + g + rr * 8;
            int di = ((const int*)sEA)[row * 20 + 18];
#pragma unroll
            for (int nt = 0; nt < 4; nt++) {
                int c = ncol + nt * 8 + tg * 2;
                asm volatile("red.global.add.v2.f32 [%0], {%1,%2};"
                             :: "l"(&g_agg[di * 128 + c]),
                                "f"(accm[nt][rr * 2 + 0]), "f"(accm[nt][rr * 2 + 1])
                             : "memory");
            }
        }
        __syncthreads();  // all warps done reading s before overwrite

        // store mm into tile (perm tf32)
#pragma unroll
        for (int rr = 0; rr < 2; rr++) {
            int row = mrow + g + rr * 8;
#pragma unroll
            for (int nt = 0; nt < 4; nt++) {
                int c = ncol + nt * 8 + tg * 2;
                int base = row * SP + (c & ~7);
                int j = c & 7;
                tile[base + (j & 3) * 2 + (j >> 2)] =
                    __uint_as_float(f2tf(accm[nt][rr * 2 + 0]));
                tile[base + ((j + 1) & 3) * 2 + ((j + 1) >> 2)] =
                    __uint_as_float(f2tf(accm[nt][rr * 2 + 1]));
            }
        }
        __syncthreads();

        // ---- GEMM2: gate = sum silu(mm@Wx1+bx1)*wx2 ----
        {
            float acc[4][4];
#pragma unroll
            for (int nt = 0; nt < 4; nt++) {
                int cb = ncol + nt * 8 + tg * 2;
                float b0v = bx1s[cb], b1v = bx1s[cb + 1];
                acc[nt][0] = b0v; acc[nt][1] = b1v;
                acc[nt][2] = b0v; acc[nt][3] = b1v;
            }
            gemm_kloop16p(tile, wtx, mrow, ncol, lane, acc);
            float p0 = 0.f, p1 = 0.f;
#pragma unroll
            for (int nt = 0; nt < 4; nt++) {
                int cb = ncol + nt * 8 + tg * 2;
                float w0 = wx2s[cb], w1 = wx2s[cb + 1];
                p0 += siluf(acc[nt][0]) * w0 + siluf(acc[nt][1]) * w1;
                p1 += siluf(acc[nt][2]) * w0 + siluf(acc[nt][3]) * w1;
            }
            p0 += __shfl_xor_sync(0xffffffffu, p0, 1);
            p0 += __shfl_xor_sync(0xffffffffu, p0, 2);
            p1 += __shfl_xor_sync(0xffffffffu, p1, 1);
            p1 += __shfl_xor_sync(0xffffffffu, p1, 2);
            if (tg == 0) {
                atomicAdd(&sgate[mrow + g], p0);
                atomicAdd(&sgate[mrow + g + 8], p1);
            }
        }
        __syncthreads();

        // ---- x scatter ----
        if (tid < 128) {
            int si = ((const int*)sEA)[tid * 20 + 17];
            int di = ((const int*)sEA)[tid * 20 + 18];
            float dx = x[di * 3 + 0] - x[si * 3 + 0];
            float dy = x[di * 3 + 1] - x[si * 3 + 1];
            float dz = x[di * 3 + 2] - x[si * 3 + 2];
            float rn = __fdividef(1.0f, sqrtf(dx * dx + dy * dy + dz * dz) + 1e-9f);
            float gte = sgate[tid];
            atomicAdd(&outx[di * 3 + 0], dx * rn * gte);
            atomicAdd(&outx[di * 3 + 1], dy * rn * gte);
            atomicAdd(&outx[di * 3 + 2], dz * rn * gte);
        }
        __syncthreads();
    }
}

// ---------------- node update (persistent, 1024 thr) ------------------------
__global__ __launch_bounds__(1024, 1) void k_node_upd(
    const float* __restrict__ h, const float* __restrict__ Wh1,
    const float* __restrict__ bh1, const float* __restrict__ Wh2,
    const float* __restrict__ bh2, const float* __restrict__ lng,
    const float* __restrict__ lnb, float* __restrict__ outh) {
    extern __shared__ float sm[];
    float* hr = sm;              // 128*SP fp32 row-major (residual + GEMM1 pass1)
    float* ap = hr + 128 * SP;   // 128*SP perm tf32 (agg, then tt)
    float* wt = ap + 128 * SP;   // weight buffer
    float* bh1s = wt + 128 * SP;
    float* bh2s = bh1s + 128;
    float* lngs = bh2s + 128;
    float* lnbs = lngs + 128;
    float* ssum = lnbs + 128;
    float* ssq = ssum + 128;

    int tid = threadIdx.x, lane = tid & 31, warp = tid >> 5;
    if (tid < 128) {
        bh1s[tid] = bh1[tid];
        bh2s[tid] = bh2[tid];
        lngs[tid] = lng[tid];
        lnbs[tid] = lnb[tid];
    }

    int mrow = (warp >> 2) * 16, ncol = (warp & 3) * 32;
    int g = lane >> 2, tg = lane & 3;

    for (int t = blockIdx.x; t < NTILE_N; t += gridDim.x) {
        int n0 = t * 128;
        if (tid < 128) {
            ssum[tid] = 0.f;
            ssq[tid] = 0.f;
        }
        // stage h (fp32) + agg (perm tf32)
#pragma unroll
        for (int v = 0; v < 4; v++) {
            int f = v * 1024 + tid;
            int r = f >> 5, c4 = (f & 31) * 4;
            float4 hv = make_float4(0.f, 0.f, 0.f, 0.f);
            float4 av = make_float4(0.f, 0.f, 0.f, 0.f);
            if (n0 + r < NN) {
                hv = *(const float4*)&h[(n0 + r) * 128 + c4];
                av = *(const float4*)&g_agg[(n0 + r) * 128 + c4];
            }
            *(float4*)&hr[r * SP + c4] = hv;
            int base = r * SP + (c4 & ~7);
            int off = (c4 & 7) >> 2;
            ap[base + 0 + off] = __uint_as_float(f2tf(av.x));
            ap[base + 2 + off] = __uint_as_float(f2tf(av.y));
            ap[base + 4 + off] = __uint_as_float(f2tf(av.z));
            ap[base + 6 + off] = __uint_as_float(f2tf(av.w));
        }
        stage_wtn(wt, Wh1, tid);
        __syncthreads();

        // GEMM1 pass1: h @ Wh1a (fp32 A, non-perm)
        float acc[4][4];
#pragma unroll
        for (int nt = 0; nt < 4; nt++) {
            int cb = ncol + nt * 8 + tg * 2;
            float b0v = bh1s[cb], b1v = bh1s[cb + 1];
            acc[nt][0] = b0v; acc[nt][1] = b1v;
            acc[nt][2] = b0v; acc[nt][3] = b1v;
        }
        gemm_kloop16n(hr, wt, mrow, ncol, lane, acc);
        __syncthreads();
        stage_wtp(wt, Wh1 + 128 * 128, tid);
        __syncthreads();
        // GEMM1 pass2: agg @ Wh1b (perm)
        gemm_kloop16p(ap, wt, mrow, ncol, lane, acc);
        __syncthreads();  // done reading ap

        // tt = silu(acc) -> ap (perm tf32)
#pragma unroll
        for (int rr = 0; rr < 2; rr++) {
            int row = mrow + g + rr * 8;
#pragma unroll
            for (int nt = 0; nt < 4; nt++) {
                int c = ncol + nt * 8 + tg * 2;
                int base = row * SP + (c & ~7);
                int j = c & 7;
                ap[base + (j & 3) * 2 + (j >> 2)] =
                    __uint_as_float(f2tf(siluf(acc[nt][rr * 2 + 0])));
                ap[base + ((j + 1) & 3) * 2 + ((j + 1) >> 2)] =
                    __uint_as_float(f2tf(siluf(acc[nt][rr * 2 + 1])));
            }
        }
        stage_wtp(wt, Wh2, tid);
        __syncthreads();

        // GEMM2: dh = tt @ Wh2 + bh2 ; v = h + dh
        float acc2[4][4];
#pragma unroll
        for (int nt = 0; nt < 4; nt++) {
            int cb = ncol + nt * 8 + tg * 2;
            float b0v = bh2s[cb], b1v = bh2s[cb + 1];
            acc2[nt][0] = b0v; acc2[nt][1] = b1v;
            acc2[nt][2] = b0v; acc2[nt][3] = b1v;
        }
        gemm_kloop16p(ap, wt, mrow, ncol, lane, acc2);

        float vsum[2] = {0.f, 0.f}, vsq[2] = {0.f, 0.f};
#pragma unroll
        for (int rr = 0; rr < 2; rr++) {
            int row = mrow + g + rr * 8;
#pragma unroll
            for (int nt = 0; nt < 4; nt++) {
                int cb = ncol + nt * 8 + tg * 2;
                float v0 = hr[row * SP + cb] + acc2[nt][rr * 2 + 0];
                float v1 = hr[row * SP + cb + 1] + acc2[nt][rr * 2 + 1];
                acc2[nt][rr * 2 + 0] = v0;
                acc2[nt][rr * 2 + 1] = v1;
                vsum[rr] += v0 + v1;
                vsq[rr] += v0 * v0 + v1 * v1;
            }
        }
#pragma unroll
        for (int i = 0; i < 2; i++) {
            vsum[i] += __shfl_xor_sync(0xffffffffu, vsum[i], 1);
            vsum[i] += __shfl_xor_sync(0xffffffffu, vsum[i], 2);
            vsq[i] += __shfl_xor_sync(0xffffffffu, vsq[i], 1);
            vsq[i] += __shfl_xor_sync(0xffffffffu, vsq[i], 2);
        }
        if (tg == 0) {
            atomicAdd(&ssum[mrow + g], vsum[0]);
            atomicAdd(&ssq[mrow + g], vsq[0]);
            atomicAdd(&ssum[mrow + g + 8], vsum[1]);
            atomicAdd(&ssq[mrow + g + 8], vsq[1]);
        }
        __syncthreads();

#pragma unroll
        for (int rr = 0; rr < 2; rr++) {
            int row = mrow + g + rr * 8;
            float mean = ssum[row] * (1.0f / 128.0f);
            float var = ssq[row] * (1.0f / 128.0f) - mean * mean;
            float rstd = rsqrtf(var + 1e-5f);
            if (n0 + row < NN) {
#pragma unroll
                for (int nt = 0; nt < 4; nt++) {
                    int cb = ncol + nt * 8 + tg * 2;
                    *(float2*)&outh[(n0 + row) * 128 + cb] = make_float2(
                        (acc2[nt][rr * 2 + 0] - mean) * rstd * lngs[cb] + lnbs[cb],
                        (acc2[nt][rr * 2 + 1] - mean) * rstd * lngs[cb + 1] + lnbs[cb + 1]);
                }
            }
        }
        __syncthreads();
    }
}

// ---------------- launcher ---------------------------------------------------
extern "C" void kernel_launch(void* const* d_in, const int* in_sizes, int n_in,
                              void* d_out, int out_size) {
    const float* h = (const float*)d_in[0];
    const float* x = (const float*)d_in[1];
    const void* ei = d_in[2];
    const float* ea = (const float*)d_in[3];
    const float* We1 = (const float*)d_in[4];
    const float* be1 = (const float*)d_in[5];
    const float* We2 = (const float*)d_in[6];
    const float* be2 = (const float*)d_in[7];
    const float* Wh1 = (const float*)d_in[8];
    const float* bh1 = (const float*)d_in[9];
    const float* Wh2 = (const float*)d_in[10];
    const float* bh2 = (const float*)d_in[11];
    const float* Wx1 = (const float*)d_in[12];
    const float* bx1 = (const float*)d_in[13];
    const float* Wx2 = (const float*)d_in[14];
    const float* bx2 = (const float*)d_in[15];
    const float* lng = (const float*)d_in[16];
    const float* lnb = (const float*)d_in[17];

    float* outh = (float*)d_out;
    float* outx = outh + (size_t)NN * 128;

    const int SMEM_EDGE = (3 * 128 * SP + 128 * 20 + 128 * 16 + 6 * 128) * 4;  // 230400
    const int SMEM_PRE = (3 * 128 * SP) * 4;                                    // 208896
    const int SMEM_UPD = (3 * 128 * SP + 6 * 128) * 4;                          // 211968
    cudaFuncSetAttribute(k_edge, cudaFuncAttributeMaxDynamicSharedMemorySize, SMEM_EDGE);
    cudaFuncSetAttribute(k_node_pre, cudaFuncAttributeMaxDynamicSharedMemorySize, SMEM_PRE);
    cudaFuncSetAttribute(k_node_upd, cudaFuncAttributeMaxDynamicSharedMemorySize, SMEM_UPD);

    k_detect<<<1, 32>>>(ei);
    k_convert<<<(EE + 255) / 256, 256>>>(ei);
    k_init<<<1024, 256>>>(x, outx);
    k_node_pre<<<PGRID, 1024, SMEM_PRE>>>(h, We1);
    k_edge<<<PGRID, 1024, SMEM_EDGE>>>(x, ea, We1, be1, We2, be2, Wx1, bx1, Wx2,
                                       bx2, outx);
    k_node_upd<<<PGRID, 1024, SMEM_UPD>>>(h, Wh1, bh1, Wh2, bh2, lng, lnb, outh);
}

// round 8
// speedup vs baseline: 1.1881x; 1.1881x over previous
#include <cuda_runtime.h>

#define NN 50000
#define EE 800000
#define SP 136
#define NTILE_E (EE / 128)
#define NTILE_N ((NN + 127) / 128)
#define PGRID 148

// ---------------- scratch (device globals) ----------------------------------
__device__ int   g_is64;
__device__ int   g_src[EE];
__device__ int   g_dst[EE];
__device__ float g_A[NN * 128];    // h @ We1[0:128]
__device__ float g_B[NN * 128];    // h @ We1[128:256]
__device__ float g_agg[NN * 128];  // segment-sum of m

__device__ __forceinline__ float siluf(float v) {
    float t;
    asm("tanh.approx.f32 %0, %1;" : "=f"(t) : "f"(0.5f * v));
    return 0.5f * v * (1.0f + t);
}

__device__ __forceinline__ unsigned f2tf(float v) {
    unsigned u;
    asm("cvt.rna.tf32.f32 %0, %1;" : "=r"(u) : "f"(v));
    return u;
}

// permuted slot of k within its 8-group: pairs (t, t+4) adjacent
__device__ __forceinline__ int kpos(int k) {
    return (k & ~7) + ((k & 3) * 2 + ((k >> 2) & 1));
}

__device__ __forceinline__ void mma8(float* c, const unsigned* a, const unsigned* b) {
    asm volatile(
        "mma.sync.aligned.m16n8k8.row.col.f32.tf32.tf32.f32 "
        "{%0,%1,%2,%3},{%4,%5,%6,%7},{%8,%9},{%0,%1,%2,%3};"
        : "+f"(c[0]), "+f"(c[1]), "+f"(c[2]), "+f"(c[3])
        : "r"(a[0]), "r"(a[1]), "r"(a[2]), "r"(a[3]), "r"(b[0]), "r"(b[1]));
}

// ---- stage weight 128x128 row-major -> WT[n][kpos(k)] tf32 (1024 thr) ------
__device__ __forceinline__ void stage_wtp(float* wt, const float* __restrict__ W,
                                          int tid) {
#pragma unroll
    for (int s = 0; s < 16; s++) {
        int i = s * 1024 + tid;
        int n = i & 127, k = i >> 7;
        wt[n * SP + kpos(k)] = __uint_as_float(f2tf(W[k * 128 + n]));
    }
}

// non-permuted staging (for fp32-A pass)
__device__ __forceinline__ void stage_wtn(float* wt, const float* __restrict__ W,
                                          int tid) {
#pragma unroll
    for (int s = 0; s < 16; s++) {
        int i = s * 1024 + tid;
        int n = i & 127, k = i >> 7;
        wt[n * SP + k] = __uint_as_float(f2tf(W[k * 128 + n]));
    }
}

// ---- permuted-tf32 k-loop: M=16, N=32, K=128 -------------------------------
__device__ __forceinline__ void gemm_kloop16p(const float* sA, const float* wt,
                                              int mrow, int ncol, int lane,
                                              float acc[4][4]) {
    int g = lane >> 2, tg = lane & 3;
    const float* ap0 = sA + (mrow + g) * SP + 2 * tg;
    const float* ap1 = ap0 + 8 * SP;
    const float* bp0 = wt + (ncol + g) * SP + 2 * tg;
#pragma unroll
    for (int kk = 0; kk < 16; kk++) {
        int k0 = kk * 8;
        float2 a02 = *(const float2*)(ap0 + k0);
        float2 a13 = *(const float2*)(ap1 + k0);
        unsigned a[4] = {__float_as_uint(a02.x), __float_as_uint(a13.x),
                         __float_as_uint(a02.y), __float_as_uint(a13.y)};
#pragma unroll
        for (int nt = 0; nt < 4; nt++) {
            float2 b = *(const float2*)(bp0 + nt * 8 * SP + k0);
            unsigned bb[2] = {__float_as_uint(b.x), __float_as_uint(b.y)};
            mma8(acc[nt], a, bb);
        }
    }
}

// ---- fp32-A non-perm k-loop: M=16, N=32, K=128 (A cvt on load) -------------
__device__ __forceinline__ void gemm_kloop16n(const float* sA, const float* wt,
                                              int mrow, int ncol, int lane,
                                              float acc[4][4]) {
    int g = lane >> 2, tg = lane & 3;
    const float* a0p = sA + (mrow + g) * SP + tg;
    const float* b0p = wt + (ncol + g) * SP + tg;
#pragma unroll
    for (int kk = 0; kk < 16; kk++) {
        int k0 = kk * 8;
        unsigned a[4];
        a[0] = f2tf(a0p[k0]);
        a[1] = f2tf(a0p[8 * SP + k0]);
        a[2] = f2tf(a0p[k0 + 4]);
        a[3] = f2tf(a0p[8 * SP + k0 + 4]);
#pragma unroll
        for (int nt = 0; nt < 4; nt++) {
            const float* bp = b0p + nt * 8 * SP + k0;
            unsigned b[2] = {__float_as_uint(bp[0]), __float_as_uint(bp[4])};
            mma8(acc[nt], a, b);
        }
    }
}

// ---------------- index dtype detection + conversion ------------------------
__global__ void k_detect(const void* ei) {
    if (blockIdx.x == 0 && threadIdx.x == 0) {
        const int* p = (const int*)ei;
        int acc = 0;
        for (int i = 0; i < 64; i++) acc |= p[2 * i + 1];
        g_is64 = (acc == 0) ? 1 : 0;
    }
}

__global__ void k_convert(const void* ei) {
    int e = blockIdx.x * blockDim.x + threadIdx.x;
    if (e >= EE) return;
    if (g_is64) {
        const long long* p = (const long long*)ei;
        g_src[e] = (int)p[e];
        g_dst[e] = (int)p[EE + e];
    } else {
        const int* p = (const int*)ei;
        g_src[e] = p[e];
        g_dst[e] = p[EE + e];
    }
}

// ---------------- init: zero agg, x_out = x ---------------------------------
__global__ void k_init(const float* __restrict__ x, float* __restrict__ outx) {
    for (int i = blockIdx.x * blockDim.x + threadIdx.x; i < NN * 128;
         i += gridDim.x * blockDim.x) {
        g_agg[i] = 0.0f;
        if (i < NN * 3) outx[i] = x[i];
    }
}

// ---------------- node pre-GEMM (persistent, 1024 thr) ----------------------
__global__ __launch_bounds__(1024, 1) void k_node_pre(
    const float* __restrict__ h, const float* __restrict__ We1) {
    extern __shared__ float sm[];
    float* ht = sm;               // 128*SP perm tf32
    float* wtA = ht + 128 * SP;
    float* wtB = wtA + 128 * SP;

    int tid = threadIdx.x, lane = tid & 31, warp = tid >> 5;
    stage_wtp(wtA, We1, tid);
    stage_wtp(wtB, We1 + 128 * 128, tid);
    __syncthreads();

    int mrow = (warp >> 2) * 16, ncol = (warp & 3) * 32;
    int g = lane >> 2, tg = lane & 3;

    for (int t = blockIdx.x; t < NTILE_N; t += gridDim.x) {
        int n0 = t * 128;
#pragma unroll
        for (int v = 0; v < 4; v++) {
            int f = v * 1024 + tid;
            int r = f >> 5, c4 = (f & 31) * 4;
            float4 val = make_float4(0.f, 0.f, 0.f, 0.f);
            if (n0 + r < NN) val = *(const float4*)&h[(n0 + r) * 128 + c4];
            int base = r * SP + (c4 & ~7);
            int off = (c4 & 7) >> 2;
            ht[base + 0 + off] = __uint_as_float(f2tf(val.x));
            ht[base + 2 + off] = __uint_as_float(f2tf(val.y));
            ht[base + 4 + off] = __uint_as_float(f2tf(val.z));
            ht[base + 6 + off] = __uint_as_float(f2tf(val.w));
        }
        __syncthreads();
#pragma unroll
        for (int half = 0; half < 2; half++) {
            float acc[4][4];
#pragma unroll
            for (int nt = 0; nt < 4; nt++)
#pragma unroll
                for (int l = 0; l < 4; l++) acc[nt][l] = 0.f;
            gemm_kloop16p(ht, half ? wtB : wtA, mrow, ncol, lane, acc);
            float* out = half ? g_B : g_A;
#pragma unroll
            for (int nt = 0; nt < 4; nt++) {
                int r = mrow + g;
                int cb = ncol + nt * 8 + tg * 2;
                if (n0 + r < NN)
                    *(float2*)&out[(n0 + r) * 128 + cb] = make_float2(acc[nt][0], acc[nt][1]);
                if (n0 + r + 8 < NN)
                    *(float2*)&out[(n0 + r + 8) * 128 + cb] = make_float2(acc[nt][2], acc[nt][3]);
            }
        }
        __syncthreads();
    }
}

// ---------------- fused edge kernel (persistent, 1024 thr) ------------------
__global__ __launch_bounds__(1024, 1) void k_edge(
    const float* __restrict__ x, const float* __restrict__ ea,
    const float* __restrict__ We1, const float* __restrict__ be1,
    const float* __restrict__ We2, const float* __restrict__ be2,
    const float* __restrict__ Wx1, const float* __restrict__ bx1,
    const float* __restrict__ Wx2, const float* __restrict__ bx2,
    float* __restrict__ outx) {
    extern __shared__ float sm[];
    float* tile = sm;                   // 128*SP (s -> mm, perm tf32)
    float* wt2 = tile + 128 * SP;       // We2^T perm
    float* wtx = wt2 + 128 * SP;        // Wx1^T perm
    float* sEA = wtx + 128 * SP;        // 128*20: ea[16]|dist|si|di|pad
    float* wtE = sEA + 128 * 20;        // 128*16: edge-attr weight block, perm
    float* wds = wtE + 128 * 16;
    float* be1s = wds + 128;
    float* be2s = be1s + 128;
    float* bx1s = be2s + 128;
    float* wx2s = bx1s + 128;
    float* sgate = wx2s + 128;          // 2*128 (double-buffered)

    int tid = threadIdx.x, lane = tid & 31, warp = tid >> 5;

    // ---- one-time staging ----
    stage_wtp(wt2, We2, tid);
    stage_wtp(wtx, Wx1, tid);
#pragma unroll
    for (int s = 0; s < 2; s++) {
        int i = s * 1024 + tid;
        int n = i & 127, k = i >> 7;
        wtE[n * 16 + kpos(k)] = __uint_as_float(f2tf(We1[(256 + k) * 128 + n]));
    }
    if (tid < 128) {
        wds[tid] = We1[272 * 128 + tid];
        be1s[tid] = be1[tid];
        be2s[tid] = be2[tid];
        bx1s[tid] = bx1[tid];
        wx2s[tid] = Wx2[tid];
    }
    float bx2v = bx2[0];

    int mrow = (warp >> 2) * 16, ncol = (warp & 3) * 32;
    int g = lane >> 2, tg = lane & 3;
    int e_l = tid >> 3, q = tid & 7;

    // ---- stage first tile ----
    {
        int e = blockIdx.x * 128 + e_l;
        *(float2*)&sEA[e_l * 20 + q * 2] = *(const float2*)&ea[e * 16 + q * 2];
        if (q == 0) {
            int si = g_src[e], di = g_dst[e];
            float dx = x[di * 3 + 0] - x[si * 3 + 0];
            float dy = x[di * 3 + 1] - x[si * 3 + 1];
            float dz = x[di * 3 + 2] - x[si * 3 + 2];
            sEA[e_l * 20 + 16] = sqrtf(dx * dx + dy * dy + dz * dz + 1e-9f);
            ((int*)sEA)[e_l * 20 + 17] = si;
            ((int*)sEA)[e_l * 20 + 18] = di;
        }
        if (tid < 128) sgate[tid] = bx2v;
    }
    __syncthreads();

    int pb = 0;
    for (int t = blockIdx.x; t < NTILE_E; t += PGRID) {
        float* sg_cur = sgate + pb * 128;
        float* sg_nxt = sgate + (pb ^ 1) * 128;
        int tn = t + PGRID;
        bool hn = tn < NTILE_E;

        // ---- ea-GEMM (K=16) + fused gather + silu -> tile (perm tf32) ----
        {
            float acc[4][4];
#pragma unroll
            for (int nt = 0; nt < 4; nt++)
#pragma unroll
                for (int l = 0; l < 4; l++) acc[nt][l] = 0.f;
            const float* a0p = sEA + (mrow + g) * 20 + tg;
            const float* b0p = wtE + (ncol + g) * 16 + 2 * tg;
#pragma unroll
            for (int kk = 0; kk < 2; kk++) {
                int k0 = kk * 8;
                unsigned a[4];
                a[0] = f2tf(a0p[k0]);
                a[1] = f2tf(a0p[8 * 20 + k0]);
                a[2] = f2tf(a0p[k0 + 4]);
                a[3] = f2tf(a0p[8 * 20 + k0 + 4]);
#pragma unroll
                for (int nt = 0; nt < 4; nt++) {
                    float2 b = *(const float2*)(b0p + nt * 8 * 16 + k0);
                    unsigned bb[2] = {__float_as_uint(b.x), __float_as_uint(b.y)};
                    mma8(acc[nt], a, bb);
                }
            }
#pragma unroll
            for (int rr = 0; rr < 2; rr++) {
                int row = mrow + g + rr * 8;
                int si = ((const int*)sEA)[row * 20 + 17];
                int di = ((const int*)sEA)[row * 20 + 18];
                float dist = sEA[row * 20 + 16];
#pragma unroll
                for (int nt = 0; nt < 4; nt++) {
                    int c = ncol + nt * 8 + tg * 2;
                    float2 a2 = *(const float2*)&g_A[si * 128 + c];
                    float2 b2 = *(const float2*)&g_B[di * 128 + c];
                    float v0 = acc[nt][rr * 2 + 0] + dist * wds[c] + be1s[c] + a2.x + b2.x;
                    float v1 = acc[nt][rr * 2 + 1] + dist * wds[c + 1] + be1s[c + 1] +
                               a2.y + b2.y;
                    int base = row * SP + (c & ~7);
                    int j = c & 7;
                    tile[base + (j & 3) * 2 + (j >> 2)] =
                        __uint_as_float(f2tf(siluf(v0)));
                    tile[base + ((j + 1) & 3) * 2 + ((j + 1) >> 2)] =
                        __uint_as_float(f2tf(siluf(v1)));
                }
            }
        }
        __syncthreads();  // A

        // ---- GEMM1: mm = s @ We2 + be2 ----
        float accm[4][4];
#pragma unroll
        for (int nt = 0; nt < 4; nt++) {
            int cb = ncol + nt * 8 + tg * 2;
            float b0v = be2s[cb], b1v = be2s[cb + 1];
            accm[nt][0] = b0v; accm[nt][1] = b1v;
            accm[nt][2] = b0v; accm[nt][3] = b1v;
        }
        gemm_kloop16p(tile, wt2, mrow, ncol, lane, accm);

        // agg scatter straight from accumulators (fire-and-forget)
#pragma unroll
        for (int rr = 0; rr < 2; rr++) {
            int row = mrow + g + rr * 8;
            int di = ((const int*)sEA)[row * 20 + 18];
#pragma unroll
            for (int nt = 0; nt < 4; nt++) {
                int c = ncol + nt * 8 + tg * 2;
                asm volatile("red.global.add.v2.f32 [%0], {%1,%2};"
                             :: "l"(&g_agg[di * 128 + c]),
                                "f"(accm[nt][rr * 2 + 0]), "f"(accm[nt][rr * 2 + 1])
                             : "memory");
            }
        }
        __syncthreads();  // B (all warps done reading s before overwrite)

        // store mm into tile (perm tf32)
#pragma unroll
        for (int rr = 0; rr < 2; rr++) {
            int row = mrow + g + rr * 8;
#pragma unroll
            for (int nt = 0; nt < 4; nt++) {
                int c = ncol + nt * 8 + tg * 2;
                int base = row * SP + (c & ~7);
                int j = c & 7;
                tile[base + (j & 3) * 2 + (j >> 2)] =
                    __uint_as_float(f2tf(accm[nt][rr * 2 + 0]));
                tile[base + ((j + 1) & 3) * 2 + ((j + 1) >> 2)] =
                    __uint_as_float(f2tf(accm[nt][rr * 2 + 1]));
            }
        }
        __syncthreads();  // C

        // ---- prefetch next tile (regs) + snapshot scatter info ----
        float2 pea;
        int psi = 0, pdi = 0;
        float pdx = 0.f, pdy = 0.f, pdz = 0.f;
        if (hn) {
            int e = tn * 128 + e_l;
            pea = *(const float2*)&ea[e * 16 + q * 2];
            if (q == 0) {
                psi = g_src[e];
                pdi = g_dst[e];
                pdx = x[pdi * 3 + 0] - x[psi * 3 + 0];
                pdy = x[pdi * 3 + 1] - x[psi * 3 + 1];
                pdz = x[pdi * 3 + 2] - x[psi * 3 + 2];
            }
        }
        int xsi = 0, xdi = 0;
        if (tid < 128) {
            xsi = ((const int*)sEA)[tid * 20 + 17];
            xdi = ((const int*)sEA)[tid * 20 + 18];
        }

        // ---- GEMM2: gate = sum silu(mm@Wx1+bx1)*wx2 ----
        {
            float acc[4][4];
#pragma unroll
            for (int nt = 0; nt < 4; nt++) {
                int cb = ncol + nt * 8 + tg * 2;
                float b0v = bx1s[cb], b1v = bx1s[cb + 1];
                acc[nt][0] = b0v; acc[nt][1] = b1v;
                acc[nt][2] = b0v; acc[nt][3] = b1v;
            }
            gemm_kloop16p(tile, wtx, mrow, ncol, lane, acc);
            float p0 = 0.f, p1 = 0.f;
#pragma unroll
            for (int nt = 0; nt < 4; nt++) {
                int cb = ncol + nt * 8 + tg * 2;
                float w0 = wx2s[cb], w1 = wx2s[cb + 1];
                p0 += siluf(acc[nt][0]) * w0 + siluf(acc[nt][1]) * w1;
                p1 += siluf(acc[nt][2]) * w0 + siluf(acc[nt][3]) * w1;
            }
            p0 += __shfl_xor_sync(0xffffffffu, p0, 1);
            p0 += __shfl_xor_sync(0xffffffffu, p0, 2);
            p1 += __shfl_xor_sync(0xffffffffu, p1, 1);
            p1 += __shfl_xor_sync(0xffffffffu, p1, 2);
            if (tg == 0) {
                atomicAdd(&sg_cur[mrow + g], p0);
                atomicAdd(&sg_cur[mrow + g + 8], p1);
            }
        }
        __syncthreads();  // D

        // ---- x scatter (snapshotted indices) + stage next tile ----
        if (tid < 128) {
            float dx = x[xdi * 3 + 0] - x[xsi * 3 + 0];
            float dy = x[xdi * 3 + 1] - x[xsi * 3 + 1];
            float dz = x[xdi * 3 + 2] - x[xsi * 3 + 2];
            float rn = __fdividef(1.0f, sqrtf(dx * dx + dy * dy + dz * dz) + 1e-9f);
            float gte = sg_cur[tid];
            atomicAdd(&outx[xdi * 3 + 0], dx * rn * gte);
            atomicAdd(&outx[xdi * 3 + 1], dy * rn * gte);
            atomicAdd(&outx[xdi * 3 + 2], dz * rn * gte);
            sg_nxt[tid] = bx2v;
        }
        if (hn) {
            *(float2*)&sEA[e_l * 20 + q * 2] = pea;
            if (q == 0) {
                sEA[e_l * 20 + 16] = sqrtf(pdx * pdx + pdy * pdy + pdz * pdz + 1e-9f);
                ((int*)sEA)[e_l * 20 + 17] = psi;
                ((int*)sEA)[e_l * 20 + 18] = pdi;
            }
        }
        __syncthreads();  // E
        pb ^= 1;
    }
}

// ---------------- node update (persistent, 1024 thr) ------------------------
__global__ __launch_bounds__(1024, 1) void k_node_upd(
    const float* __restrict__ h, const float* __restrict__ Wh1,
    const float* __restrict__ bh1, const float* __restrict__ Wh2,
    const float* __restrict__ bh2, const float* __restrict__ lng,
    const float* __restrict__ lnb, float* __restrict__ outh) {
    extern __shared__ float sm[];
    float* hr = sm;              // 128*SP fp32 row-major (residual + GEMM1 pass1)
    float* ap = hr + 128 * SP;   // 128*SP perm tf32 (agg, then tt)
    float* wt = ap + 128 * SP;   // weight buffer
    float* bh1s = wt + 128 * SP;
    float* bh2s = bh1s + 128;
    float* lngs = bh2s + 128;
    float* lnbs = lngs + 128;
    float* ssum = lnbs + 128;
    float* ssq = ssum + 128;

    int tid = threadIdx.x, lane = tid & 31, warp = tid >> 5;
    if (tid < 128) {
        bh1s[tid] = bh1[tid];
        bh2s[tid] = bh2[tid];
        lngs[tid] = lng[tid];
        lnbs[tid] = lnb[tid];
    }

    int mrow = (warp >> 2) * 16, ncol = (warp & 3) * 32;
    int g = lane >> 2, tg = lane & 3;

    for (int t = blockIdx.x; t < NTILE_N; t += gridDim.x) {
        int n0 = t * 128;
        if (tid < 128) {
            ssum[tid] = 0.f;
            ssq[tid] = 0.f;
        }
#pragma unroll
        for (int v = 0; v < 4; v++) {
            int f = v * 1024 + tid;
            int r = f >> 5, c4 = (f & 31) * 4;
            float4 hv = make_float4(0.f, 0.f, 0.f, 0.f);
            float4 av = make_float4(0.f, 0.f, 0.f, 0.f);
            if (n0 + r < NN) {
                hv = *(const float4*)&h[(n0 + r) * 128 + c4];
                av = *(const float4*)&g_agg[(n0 + r) * 128 + c4];
            }
            *(float4*)&hr[r * SP + c4] = hv;
            int base = r * SP + (c4 & ~7);
            int off = (c4 & 7) >> 2;
            ap[base + 0 + off] = __uint_as_float(f2tf(av.x));
            ap[base + 2 + off] = __uint_as_float(f2tf(av.y));
            ap[base + 4 + off] = __uint_as_float(f2tf(av.z));
            ap[base + 6 + off] = __uint_as_float(f2tf(av.w));
        }
        stage_wtn(wt, Wh1, tid);
        __syncthreads();

        // GEMM1 pass1: h @ Wh1a (fp32 A, non-perm)
        float acc[4][4];
#pragma unroll
        for (int nt = 0; nt < 4; nt++) {
            int cb = ncol + nt * 8 + tg * 2;
            float b0v = bh1s[cb], b1v = bh1s[cb + 1];
            acc[nt][0] = b0v; acc[nt][1] = b1v;
            acc[nt][2] = b0v; acc[nt][3] = b1v;
        }
        gemm_kloop16n(hr, wt, mrow, ncol, lane, acc);
        __syncthreads();
        stage_wtp(wt, Wh1 + 128 * 128, tid);
        __syncthreads();
        // GEMM1 pass2: agg @ Wh1b (perm)
        gemm_kloop16p(ap, wt, mrow, ncol, lane, acc);
        __syncthreads();

        // tt = silu(acc) -> ap (perm tf32)
#pragma unroll
        for (int rr = 0; rr < 2; rr++) {
            int row = mrow + g + rr * 8;
#pragma unroll
            for (int nt = 0; nt < 4; nt++) {
                int c = ncol + nt * 8 + tg * 2;
                int base = row * SP + (c & ~7);
                int j = c & 7;
                ap[base + (j & 3) * 2 + (j >> 2)] =
                    __uint_as_float(f2tf(siluf(acc[nt][rr * 2 + 0])));
                ap[base + ((j + 1) & 3) * 2 + ((j + 1) >> 2)] =
                    __uint_as_float(f2tf(siluf(acc[nt][rr * 2 + 1])));
            }
        }
        stage_wtp(wt, Wh2, tid);
        __syncthreads();

        // GEMM2: dh = tt @ Wh2 + bh2 ; v = h + dh
        float acc2[4][4];
#pragma unroll
        for (int nt = 0; nt < 4; nt++) {
            int cb = ncol + nt * 8 + tg * 2;
            float b0v = bh2s[cb], b1v = bh2s[cb + 1];
            acc2[nt][0] = b0v; acc2[nt][1] = b1v;
            acc2[nt][2] = b0v; acc2[nt][3] = b1v;
        }
        gemm_kloop16p(ap, wt, mrow, ncol, lane, acc2);

        float vsum[2] = {0.f, 0.f}, vsq[2] = {0.f, 0.f};
#pragma unroll
        for (int rr = 0; rr < 2; rr++) {
            int row = mrow + g + rr * 8;
#pragma unroll
            for (int nt = 0; nt < 4; nt++) {
                int cb = ncol + nt * 8 + tg * 2;
                float v0 = hr[row * SP + cb] + acc2[nt][rr * 2 + 0];
                float v1 = hr[row * SP + cb + 1] + acc2[nt][rr * 2 + 1];
                acc2[nt][rr * 2 + 0] = v0;
                acc2[nt][rr * 2 + 1] = v1;
                vsum[rr] += v0 + v1;
                vsq[rr] += v0 * v0 + v1 * v1;
            }
        }
#pragma unroll
        for (int i = 0; i < 2; i++) {
            vsum[i] += __shfl_xor_sync(0xffffffffu, vsum[i], 1);
            vsum[i] += __shfl_xor_sync(0xffffffffu, vsum[i], 2);
            vsq[i] += __shfl_xor_sync(0xffffffffu, vsq[i], 1);
            vsq[i] += __shfl_xor_sync(0xffffffffu, vsq[i], 2);
        }
        if (tg == 0) {
            atomicAdd(&ssum[mrow + g], vsum[0]);
            atomicAdd(&ssq[mrow + g], vsq[0]);
            atomicAdd(&ssum[mrow + g + 8], vsum[1]);
            atomicAdd(&ssq[mrow + g + 8], vsq[1]);
        }
        __syncthreads();

#pragma unroll
        for (int rr = 0; rr < 2; rr++) {
            int row = mrow + g + rr * 8;
            float mean = ssum[row] * (1.0f / 128.0f);
            float var = ssq[row] * (1.0f / 128.0f) - mean * mean;
            float rstd = rsqrtf(var + 1e-5f);
            if (n0 + row < NN) {
#pragma unroll
                for (int nt = 0; nt < 4; nt++) {
                    int cb = ncol + nt * 8 + tg * 2;
                    *(float2*)&outh[(n0 + row) * 128 + cb] = make_float2(
                        (acc2[nt][rr * 2 + 0] - mean) * rstd * lngs[cb] + lnbs[cb],
                        (acc2[nt][rr * 2 + 1] - mean) * rstd * lngs[cb + 1] + lnbs[cb + 1]);
                }
            }
        }
        __syncthreads();
    }
}

// ---------------- launcher ---------------------------------------------------
extern "C" void kernel_launch(void* const* d_in, const int* in_sizes, int n_in,
                              void* d_out, int out_size) {
    const float* h = (const float*)d_in[0];
    const float* x = (const float*)d_in[1];
    const void* ei = d_in[2];
    const float* ea = (const float*)d_in[3];
    const float* We1 = (const float*)d_in[4];
    const float* be1 = (const float*)d_in[5];
    const float* We2 = (const float*)d_in[6];
    const float* be2 = (const float*)d_in[7];
    const float* Wh1 = (const float*)d_in[8];
    const float* bh1 = (const float*)d_in[9];
    const float* Wh2 = (const float*)d_in[10];
    const float* bh2 = (const float*)d_in[11];
    const float* Wx1 = (const float*)d_in[12];
    const float* bx1 = (const float*)d_in[13];
    const float* Wx2 = (const float*)d_in[14];
    const float* bx2 = (const float*)d_in[15];
    const float* lng = (const float*)d_in[16];
    const float* lnb = (const float*)d_in[17];

    float* outh = (float*)d_out;
    float* outx = outh + (size_t)NN * 128;

    const int SMEM_EDGE = (3 * 128 * SP + 128 * 20 + 128 * 16 + 5 * 128 + 256) * 4;  // 230912
    const int SMEM_PRE = (3 * 128 * SP) * 4;                                          // 208896
    const int SMEM_UPD = (3 * 128 * SP + 6 * 128) * 4;                                // 211968
    cudaFuncSetAttribute(k_edge, cudaFuncAttributeMaxDynamicSharedMemorySize, SMEM_EDGE);
    cudaFuncSetAttribute(k_node_pre, cudaFuncAttributeMaxDynamicSharedMemorySize, SMEM_PRE);
    cudaFuncSetAttribute(k_node_upd, cudaFuncAttributeMaxDynamicSharedMemorySize, SMEM_UPD);

    k_detect<<<1, 32>>>(ei);
    k_convert<<<(EE + 255) / 256, 256>>>(ei);
    k_init<<<1024, 256>>>(x, outx);
    k_node_pre<<<PGRID, 1024, SMEM_PRE>>>(h, We1);
    k_edge<<<PGRID, 1024, SMEM_EDGE>>>(x, ea, We1, be1, We2, be2, Wx1, bx1, Wx2,
                                       bx2, outx);
    k_node_upd<<<PGRID, 1024, SMEM_UPD>>>(h, Wh1, bh1, Wh2, bh2, lng, lnb, outh);
}

// round 9
// speedup vs baseline: 1.2752x; 1.0734x over previous
#include <cuda_runtime.h>

#define NN 50000
#define EE 800000
#define SP 136
#define NTILE_E (EE / 128)
#define NTILE_N ((NN + 127) / 128)
#define PGRID 148

// ---------------- scratch (device globals) ----------------------------------
__device__ int   g_is64;
__device__ int   g_src[EE];
__device__ int   g_dst[EE];
__device__ float g_A[NN * 128];    // h @ We1[0:128]
__device__ float g_B[NN * 128];    // h @ We1[128:256]
__device__ float g_agg[NN * 128];  // segment-sum of m

__device__ __forceinline__ float siluf(float v) {
    float t;
    asm("tanh.approx.f32 %0, %1;" : "=f"(t) : "f"(0.5f * v));
    return 0.5f * v * (1.0f + t);
}

__device__ __forceinline__ unsigned f2tf(float v) {
    unsigned u;
    asm("cvt.rna.tf32.f32 %0, %1;" : "=r"(u) : "f"(v));
    return u;
}

// permuted slot of k within its 8-group: pairs (t, t+4) adjacent
__device__ __forceinline__ int kpos(int k) {
    return (k & ~7) + ((k & 3) * 2 + ((k >> 2) & 1));
}

__device__ __forceinline__ void mma8(float* c, const unsigned* a, const unsigned* b) {
    asm volatile(
        "mma.sync.aligned.m16n8k8.row.col.f32.tf32.tf32.f32 "
        "{%0,%1,%2,%3},{%4,%5,%6,%7},{%8,%9},{%0,%1,%2,%3};"
        : "+f"(c[0]), "+f"(c[1]), "+f"(c[2]), "+f"(c[3])
        : "r"(a[0]), "r"(a[1]), "r"(a[2]), "r"(a[3]), "r"(b[0]), "r"(b[1]));
}

// ---- stage weight 128x128 row-major -> WT[n][kpos(k)] tf32 ----------------
__device__ __forceinline__ void stage_wtp1024(float* wt, const float* __restrict__ W,
                                              int tid) {
#pragma unroll
    for (int s = 0; s < 16; s++) {
        int i = s * 1024 + tid;
        int n = i & 127, k = i >> 7;
        wt[n * SP + kpos(k)] = __uint_as_float(f2tf(W[k * 128 + n]));
    }
}

__device__ __forceinline__ void stage_wtp512(float* wt, const float* __restrict__ W,
                                             int tid) {
#pragma unroll
    for (int s = 0; s < 32; s++) {
        int i = s * 512 + tid;
        int n = i & 127, k = i >> 7;
        wt[n * SP + kpos(k)] = __uint_as_float(f2tf(W[k * 128 + n]));
    }
}

// non-permuted staging (for fp32-A pass, 1024 thr)
__device__ __forceinline__ void stage_wtn1024(float* wt, const float* __restrict__ W,
                                              int tid) {
#pragma unroll
    for (int s = 0; s < 16; s++) {
        int i = s * 1024 + tid;
        int n = i & 127, k = i >> 7;
        wt[n * SP + k] = __uint_as_float(f2tf(W[k * 128 + n]));
    }
}

// ---- permuted-tf32 k-loop: M=16, N=32, K=128 (node kernels) ---------------
__device__ __forceinline__ void gemm_kloop16p(const float* sA, const float* wt,
                                              int mrow, int ncol, int lane,
                                              float acc[4][4]) {
    int g = lane >> 2, tg = lane & 3;
    const float* ap0 = sA + (mrow + g) * SP + 2 * tg;
    const float* ap1 = ap0 + 8 * SP;
    const float* bp0 = wt + (ncol + g) * SP + 2 * tg;
#pragma unroll
    for (int kk = 0; kk < 16; kk++) {
        int k0 = kk * 8;
        float2 a02 = *(const float2*)(ap0 + k0);
        float2 a13 = *(const float2*)(ap1 + k0);
        unsigned a[4] = {__float_as_uint(a02.x), __float_as_uint(a13.x),
                         __float_as_uint(a02.y), __float_as_uint(a13.y)};
#pragma unroll
        for (int nt = 0; nt < 4; nt++) {
            float2 b = *(const float2*)(bp0 + nt * 8 * SP + k0);
            unsigned bb[2] = {__float_as_uint(b.x), __float_as_uint(b.y)};
            mma8(acc[nt], a, bb);
        }
    }
}

// ---- permuted-tf32 k-loop: M=32, N=32, K=128 (edge kernel) ----------------
// acc2[0] = rows mrow..mrow+15, acc2[1] = rows mrow+16..mrow+31
__device__ __forceinline__ void gemm_kloop32p(const float* sA, const float* wt,
                                              int mrow, int ncol, int lane,
                                              float accA[4][4], float accB[4][4]) {
    int g = lane >> 2, tg = lane & 3;
    const float* ap0 = sA + (mrow + g) * SP + 2 * tg;
    const float* ap1 = ap0 + 8 * SP;
    const float* ap2 = ap0 + 16 * SP;
    const float* ap3 = ap0 + 24 * SP;
    const float* bp0 = wt + (ncol + g) * SP + 2 * tg;
#pragma unroll
    for (int kk = 0; kk < 16; kk++) {
        int k0 = kk * 8;
        float2 a01 = *(const float2*)(ap0 + k0);
        float2 a11 = *(const float2*)(ap1 + k0);
        float2 a21 = *(const float2*)(ap2 + k0);
        float2 a31 = *(const float2*)(ap3 + k0);
        unsigned aA[4] = {__float_as_uint(a01.x), __float_as_uint(a11.x),
                          __float_as_uint(a01.y), __float_as_uint(a11.y)};
        unsigned aB[4] = {__float_as_uint(a21.x), __float_as_uint(a31.x),
                          __float_as_uint(a21.y), __float_as_uint(a31.y)};
#pragma unroll
        for (int nt = 0; nt < 4; nt++) {
            float2 b = *(const float2*)(bp0 + nt * 8 * SP + k0);
            unsigned bb[2] = {__float_as_uint(b.x), __float_as_uint(b.y)};
            mma8(accA[nt], aA, bb);
            mma8(accB[nt], aB, bb);
        }
    }
}

// ---- fp32-A non-perm k-loop: M=16, N=32, K=128 (node_upd pass1) -----------
__device__ __forceinline__ void gemm_kloop16n(const float* sA, const float* wt,
                                              int mrow, int ncol, int lane,
                                              float acc[4][4]) {
    int g = lane >> 2, tg = lane & 3;
    const float* a0p = sA + (mrow + g) * SP + tg;
    const float* b0p = wt + (ncol + g) * SP + tg;
#pragma unroll
    for (int kk = 0; kk < 16; kk++) {
        int k0 = kk * 8;
        unsigned a[4];
        a[0] = f2tf(a0p[k0]);
        a[1] = f2tf(a0p[8 * SP + k0]);
        a[2] = f2tf(a0p[k0 + 4]);
        a[3] = f2tf(a0p[8 * SP + k0 + 4]);
#pragma unroll
        for (int nt = 0; nt < 4; nt++) {
            const float* bp = b0p + nt * 8 * SP + k0;
            unsigned b[2] = {__float_as_uint(bp[0]), __float_as_uint(bp[4])};
            mma8(acc[nt], a, b);
        }
    }
}

// ---------------- index dtype detection + conversion ------------------------
__global__ void k_detect(const void* ei) {
    if (blockIdx.x == 0 && threadIdx.x == 0) {
        const int* p = (const int*)ei;
        int acc = 0;
        for (int i = 0; i < 64; i++) acc |= p[2 * i + 1];
        g_is64 = (acc == 0) ? 1 : 0;
    }
}

__global__ void k_convert(const void* ei) {
    int e = blockIdx.x * blockDim.x + threadIdx.x;
    if (e >= EE) return;
    if (g_is64) {
        const long long* p = (const long long*)ei;
        g_src[e] = (int)p[e];
        g_dst[e] = (int)p[EE + e];
    } else {
        const int* p = (const int*)ei;
        g_src[e] = p[e];
        g_dst[e] = p[EE + e];
    }
}

// ---------------- init: zero agg, x_out = x ---------------------------------
__global__ void k_init(const float* __restrict__ x, float* __restrict__ outx) {
    for (int i = blockIdx.x * blockDim.x + threadIdx.x; i < NN * 128;
         i += gridDim.x * blockDim.x) {
        g_agg[i] = 0.0f;
        if (i < NN * 3) outx[i] = x[i];
    }
}

// ---------------- node pre-GEMM (persistent, 1024 thr) ----------------------
__global__ __launch_bounds__(1024, 1) void k_node_pre(
    const float* __restrict__ h, const float* __restrict__ We1) {
    extern __shared__ float sm[];
    float* ht = sm;               // 128*SP perm tf32
    float* wtA = ht + 128 * SP;
    float* wtB = wtA + 128 * SP;

    int tid = threadIdx.x, lane = tid & 31, warp = tid >> 5;
    stage_wtp1024(wtA, We1, tid);
    stage_wtp1024(wtB, We1 + 128 * 128, tid);
    __syncthreads();

    int mrow = (warp >> 2) * 16, ncol = (warp & 3) * 32;
    int g = lane >> 2, tg = lane & 3;

    for (int t = blockIdx.x; t < NTILE_N; t += gridDim.x) {
        int n0 = t * 128;
#pragma unroll
        for (int v = 0; v < 4; v++) {
            int f = v * 1024 + tid;
            int r = f >> 5, c4 = (f & 31) * 4;
            float4 val = make_float4(0.f, 0.f, 0.f, 0.f);
            if (n0 + r < NN) val = *(const float4*)&h[(n0 + r) * 128 + c4];
            int base = r * SP + (c4 & ~7);
            int off = (c4 & 7) >> 2;
            ht[base + 0 + off] = __uint_as_float(f2tf(val.x));
            ht[base + 2 + off] = __uint_as_float(f2tf(val.y));
            ht[base + 4 + off] = __uint_as_float(f2tf(val.z));
            ht[base + 6 + off] = __uint_as_float(f2tf(val.w));
        }
        __syncthreads();
#pragma unroll
        for (int half = 0; half < 2; half++) {
            float acc[4][4];
#pragma unroll
            for (int nt = 0; nt < 4; nt++)
#pragma unroll
                for (int l = 0; l < 4; l++) acc[nt][l] = 0.f;
            gemm_kloop16p(ht, half ? wtB : wtA, mrow, ncol, lane, acc);
            float* out = half ? g_B : g_A;
#pragma unroll
            for (int nt = 0; nt < 4; nt++) {
                int r = mrow + g;
                int cb = ncol + nt * 8 + tg * 2;
                if (n0 + r < NN)
                    *(float2*)&out[(n0 + r) * 128 + cb] = make_float2(acc[nt][0], acc[nt][1]);
                if (n0 + r + 8 < NN)
                    *(float2*)&out[(n0 + r + 8) * 128 + cb] = make_float2(acc[nt][2], acc[nt][3]);
            }
        }
        __syncthreads();
    }
}

// ---------------- fused edge kernel (persistent, 512 thr, M=32 tiles) -------
__global__ __launch_bounds__(512, 1) void k_edge(
    const float* __restrict__ x, const float* __restrict__ ea,
    const float* __restrict__ We1, const float* __restrict__ be1,
    const float* __restrict__ We2, const float* __restrict__ be2,
    const float* __restrict__ Wx1, const float* __restrict__ bx1,
    const float* __restrict__ Wx2, const float* __restrict__ bx2,
    float* __restrict__ outx) {
    extern __shared__ float sm[];
    float* tile = sm;                   // 128*SP (s -> mm, perm tf32)
    float* wt2 = tile + 128 * SP;       // We2^T perm
    float* wtx = wt2 + 128 * SP;        // Wx1^T perm
    float* sEA = wtx + 128 * SP;        // 128*20: ea[16]|dist|si|di|pad
    float* wtE = sEA + 128 * 20;        // 128*16: edge-attr weight block, perm
    float* wds = wtE + 128 * 16;
    float* be1s = wds + 128;
    float* be2s = be1s + 128;
    float* bx1s = be2s + 128;
    float* wx2s = bx1s + 128;
    float* sgate = wx2s + 128;          // 2*128 (double-buffered)

    int tid = threadIdx.x, lane = tid & 31, warp = tid >> 5;

    // ---- one-time staging ----
    stage_wtp512(wt2, We2, tid);
    stage_wtp512(wtx, Wx1, tid);
#pragma unroll
    for (int s = 0; s < 4; s++) {
        int i = s * 512 + tid;
        int n = i & 127, k = i >> 7;
        wtE[n * 16 + kpos(k)] = __uint_as_float(f2tf(We1[(256 + k) * 128 + n]));
    }
    if (tid < 128) {
        wds[tid] = We1[272 * 128 + tid];
        be1s[tid] = be1[tid];
        be2s[tid] = be2[tid];
        bx1s[tid] = bx1[tid];
        wx2s[tid] = Wx2[tid];
    }
    float bx2v = bx2[0];

    // warp tile: M=32 (rows mrow..mrow+31), N=32
    int mrow = (warp & 3) * 32, ncol = (warp >> 2) * 32;
    int g = lane >> 2, tg = lane & 3;
    int e_l = tid >> 2, q = tid & 3;   // 4 threads per edge row for staging

    // ---- stage first tile ----
    {
        int e = blockIdx.x * 128 + e_l;
        *(float4*)&sEA[e_l * 20 + q * 4] = *(const float4*)&ea[e * 16 + q * 4];
        if (q == 0) {
            int si = g_src[e], di = g_dst[e];
            float dx = x[di * 3 + 0] - x[si * 3 + 0];
            float dy = x[di * 3 + 1] - x[si * 3 + 1];
            float dz = x[di * 3 + 2] - x[si * 3 + 2];
            sEA[e_l * 20 + 16] = sqrtf(dx * dx + dy * dy + dz * dz + 1e-9f);
            ((int*)sEA)[e_l * 20 + 17] = si;
            ((int*)sEA)[e_l * 20 + 18] = di;
        }
        if (tid < 128) sgate[tid] = bx2v;
    }
    __syncthreads();

    int pb = 0;
    for (int t = blockIdx.x; t < NTILE_E; t += PGRID) {
        float* sg_cur = sgate + pb * 128;
        float* sg_nxt = sgate + (pb ^ 1) * 128;
        int tn = t + PGRID;
        bool hn = tn < NTILE_E;

        // ---- ea-GEMM (K=16, M=32) + fused gather + silu -> tile (perm tf32) -
        {
            float accA[4][4], accB[4][4];
#pragma unroll
            for (int nt = 0; nt < 4; nt++)
#pragma unroll
                for (int l = 0; l < 4; l++) { accA[nt][l] = 0.f; accB[nt][l] = 0.f; }
            const float* a0p = sEA + (mrow + g) * 20 + tg;
            const float* b0p = wtE + (ncol + g) * 16 + 2 * tg;
#pragma unroll
            for (int kk = 0; kk < 2; kk++) {
                int k0 = kk * 8;
                unsigned aA[4], aB[4];
                aA[0] = f2tf(a0p[k0]);
                aA[1] = f2tf(a0p[8 * 20 + k0]);
                aA[2] = f2tf(a0p[k0 + 4]);
                aA[3] = f2tf(a0p[8 * 20 + k0 + 4]);
                aB[0] = f2tf(a0p[16 * 20 + k0]);
                aB[1] = f2tf(a0p[24 * 20 + k0]);
                aB[2] = f2tf(a0p[16 * 20 + k0 + 4]);
                aB[3] = f2tf(a0p[24 * 20 + k0 + 4]);
#pragma unroll
                for (int nt = 0; nt < 4; nt++) {
                    float2 b = *(const float2*)(b0p + nt * 8 * 16 + k0);
                    unsigned bb[2] = {__float_as_uint(b.x), __float_as_uint(b.y)};
                    mma8(accA[nt], aA, bb);
                    mma8(accB[nt], aB, bb);
                }
            }
#pragma unroll
            for (int rr = 0; rr < 4; rr++) {
                int row = mrow + g + rr * 8;
                float* ac = (rr < 2) ? &accA[0][0] : &accB[0][0];
                int jo = (rr & 1) * 2;  // 0 for rows g/g+16, 2 for rows g+8/g+24
                int si = ((const int*)sEA)[row * 20 + 17];
                int di = ((const int*)sEA)[row * 20 + 18];
                float dist = sEA[row * 20 + 16];
#pragma unroll
                for (int nt = 0; nt < 4; nt++) {
                    int c = ncol + nt * 8 + tg * 2;
                    float2 a2 = *(const float2*)&g_A[si * 128 + c];
                    float2 b2 = *(const float2*)&g_B[di * 128 + c];
                    float v0 = ac[nt * 4 + jo + 0] + dist * wds[c] + be1s[c] + a2.x + b2.x;
                    float v1 = ac[nt * 4 + jo + 1] + dist * wds[c + 1] + be1s[c + 1] +
                               a2.y + b2.y;
                    int base = row * SP + (c & ~7);
                    int j = c & 7;
                    tile[base + (j & 3) * 2 + (j >> 2)] =
                        __uint_as_float(f2tf(siluf(v0)));
                    tile[base + ((j + 1) & 3) * 2 + ((j + 1) >> 2)] =
                        __uint_as_float(f2tf(siluf(v1)));
                }
            }
        }
        __syncthreads();  // A

        // ---- GEMM1: mm = s @ We2 + be2 ----
        float accmA[4][4], accmB[4][4];
#pragma unroll
        for (int nt = 0; nt < 4; nt++) {
            int cb = ncol + nt * 8 + tg * 2;
            float b0v = be2s[cb], b1v = be2s[cb + 1];
            accmA[nt][0] = b0v; accmA[nt][1] = b1v;
            accmA[nt][2] = b0v; accmA[nt][3] = b1v;
            accmB[nt][0] = b0v; accmB[nt][1] = b1v;
            accmB[nt][2] = b0v; accmB[nt][3] = b1v;
        }
        gemm_kloop32p(tile, wt2, mrow, ncol, lane, accmA, accmB);

        // agg scatter straight from accumulators (fire-and-forget)
#pragma unroll
        for (int rr = 0; rr < 4; rr++) {
            int row = mrow + g + rr * 8;
            const float* ac = (rr < 2) ? &accmA[0][0] : &accmB[0][0];
            int jo = (rr & 1) * 2;
            int di = ((const int*)sEA)[row * 20 + 18];
#pragma unroll
            for (int nt = 0; nt < 4; nt++) {
                int c = ncol + nt * 8 + tg * 2;
                asm volatile("red.global.add.v2.f32 [%0], {%1,%2};"
                             :: "l"(&g_agg[di * 128 + c]),
                                "f"(ac[nt * 4 + jo + 0]), "f"(ac[nt * 4 + jo + 1])
                             : "memory");
            }
        }
        __syncthreads();  // B (all warps done reading s before overwrite)

        // store mm into tile (perm tf32)
#pragma unroll
        for (int rr = 0; rr < 4; rr++) {
            int row = mrow + g + rr * 8;
            const float* ac = (rr < 2) ? &accmA[0][0] : &accmB[0][0];
            int jo = (rr & 1) * 2;
#pragma unroll
            for (int nt = 0; nt < 4; nt++) {
                int c = ncol + nt * 8 + tg * 2;
                int base = row * SP + (c & ~7);
                int j = c & 7;
                tile[base + (j & 3) * 2 + (j >> 2)] =
                    __uint_as_float(f2tf(ac[nt * 4 + jo + 0]));
                tile[base + ((j + 1) & 3) * 2 + ((j + 1) >> 2)] =
                    __uint_as_float(f2tf(ac[nt * 4 + jo + 1]));
            }
        }
        __syncthreads();  // C

        // ---- prefetch next tile (regs) + snapshot scatter info ----
        float4 pea;
        int psi = 0, pdi = 0;
        float pdx = 0.f, pdy = 0.f, pdz = 0.f;
        if (hn) {
            int e = tn * 128 + e_l;
            pea = *(const float4*)&ea[e * 16 + q * 4];
            if (q == 0) {
                psi = g_src[e];
                pdi = g_dst[e];
                pdx = x[pdi * 3 + 0] - x[psi * 3 + 0];
                pdy = x[pdi * 3 + 1] - x[psi * 3 + 1];
                pdz = x[pdi * 3 + 2] - x[psi * 3 + 2];
            }
        }
        int xsi = 0, xdi = 0;
        if (tid < 128) {
            xsi = ((const int*)sEA)[tid * 20 + 17];
            xdi = ((const int*)sEA)[tid * 20 + 18];
        }

        // ---- GEMM2: gate = sum silu(mm@Wx1+bx1)*wx2 ----
        {
            float accA[4][4], accB[4][4];
#pragma unroll
            for (int nt = 0; nt < 4; nt++) {
                int cb = ncol + nt * 8 + tg * 2;
                float b0v = bx1s[cb], b1v = bx1s[cb + 1];
                accA[nt][0] = b0v; accA[nt][1] = b1v;
                accA[nt][2] = b0v; accA[nt][3] = b1v;
                accB[nt][0] = b0v; accB[nt][1] = b1v;
                accB[nt][2] = b0v; accB[nt][3] = b1v;
            }
            gemm_kloop32p(tile, wtx, mrow, ncol, lane, accA, accB);
            float p[4] = {0.f, 0.f, 0.f, 0.f};
#pragma unroll
            for (int nt = 0; nt < 4; nt++) {
                int cb = ncol + nt * 8 + tg * 2;
                float w0 = wx2s[cb], w1 = wx2s[cb + 1];
                p[0] += siluf(accA[nt][0]) * w0 + siluf(accA[nt][1]) * w1;
                p[1] += siluf(accA[nt][2]) * w0 + siluf(accA[nt][3]) * w1;
                p[2] += siluf(accB[nt][0]) * w0 + siluf(accB[nt][1]) * w1;
                p[3] += siluf(accB[nt][2]) * w0 + siluf(accB[nt][3]) * w1;
            }
#pragma unroll
            for (int i = 0; i < 4; i++) {
                p[i] += __shfl_xor_sync(0xffffffffu, p[i], 1);
                p[i] += __shfl_xor_sync(0xffffffffu, p[i], 2);
            }
            if (tg == 0) {
                atomicAdd(&sg_cur[mrow + g], p[0]);
                atomicAdd(&sg_cur[mrow + g + 8], p[1]);
                atomicAdd(&sg_cur[mrow + g + 16], p[2]);
                atomicAdd(&sg_cur[mrow + g + 24], p[3]);
            }
        }
        __syncthreads();  // D

        // ---- x scatter (snapshotted indices) + stage next tile ----
        if (tid < 128) {
            float dx = x[xdi * 3 + 0] - x[xsi * 3 + 0];
            float dy = x[xdi * 3 + 1] - x[xsi * 3 + 1];
            float dz = x[xdi * 3 + 2] - x[xsi * 3 + 2];
            float rn = __fdividef(1.0f, sqrtf(dx * dx + dy * dy + dz * dz) + 1e-9f);
            float gte = sg_cur[tid];
            atomicAdd(&outx[xdi * 3 + 0], dx * rn * gte);
            atomicAdd(&outx[xdi * 3 + 1], dy * rn * gte);
            atomicAdd(&outx[xdi * 3 + 2], dz * rn * gte);
            sg_nxt[tid] = bx2v;
        }
        if (hn) {
            *(float4*)&sEA[e_l * 20 + q * 4] = pea;
            if (q == 0) {
                sEA[e_l * 20 + 16] = sqrtf(pdx * pdx + pdy * pdy + pdz * pdz + 1e-9f);
                ((int*)sEA)[e_l * 20 + 17] = psi;
                ((int*)sEA)[e_l * 20 + 18] = pdi;
            }
        }
        __syncthreads();  // E
        pb ^= 1;
    }
}

// ---------------- node update (persistent, 1024 thr) ------------------------
__global__ __launch_bounds__(1024, 1) void k_node_upd(
    const float* __restrict__ h, const float* __restrict__ Wh1,
    const float* __restrict__ bh1, const float* __restrict__ Wh2,
    const float* __restrict__ bh2, const float* __restrict__ lng,
    const float* __restrict__ lnb, float* __restrict__ outh) {
    extern __shared__ float sm[];
    float* hr = sm;              // 128*SP fp32 row-major (residual + GEMM1 pass1)
    float* ap = hr + 128 * SP;   // 128*SP perm tf32 (agg, then tt)
    float* wt = ap + 128 * SP;   // weight buffer
    float* bh1s = wt + 128 * SP;
    float* bh2s = bh1s + 128;
    float* lngs = bh2s + 128;
    float* lnbs = lngs + 128;
    float* ssum = lnbs + 128;
    float* ssq = ssum + 128;

    int tid = threadIdx.x, lane = tid & 31, warp = tid >> 5;
    if (tid < 128) {
        bh1s[tid] = bh1[tid];
        bh2s[tid] = bh2[tid];
        lngs[tid] = lng[tid];
        lnbs[tid] = lnb[tid];
    }

    int mrow = (warp >> 2) * 16, ncol = (warp & 3) * 32;
    int g = lane >> 2, tg = lane & 3;

    for (int t = blockIdx.x; t < NTILE_N; t += gridDim.x) {
        int n0 = t * 128;
        if (tid < 128) {
            ssum[tid] = 0.f;
            ssq[tid] = 0.f;
        }
#pragma unroll
        for (int v = 0; v < 4; v++) {
            int f = v * 1024 + tid;
            int r = f >> 5, c4 = (f & 31) * 4;
            float4 hv = make_float4(0.f, 0.f, 0.f, 0.f);
            float4 av = make_float4(0.f, 0.f, 0.f, 0.f);
            if (n0 + r < NN) {
                hv = *(const float4*)&h[(n0 + r) * 128 + c4];
                av = *(const float4*)&g_agg[(n0 + r) * 128 + c4];
            }
            *(float4*)&hr[r * SP + c4] = hv;
            int base = r * SP + (c4 & ~7);
            int off = (c4 & 7) >> 2;
            ap[base + 0 + off] = __uint_as_float(f2tf(av.x));
            ap[base + 2 + off] = __uint_as_float(f2tf(av.y));
            ap[base + 4 + off] = __uint_as_float(f2tf(av.z));
            ap[base + 6 + off] = __uint_as_float(f2tf(av.w));
        }
        stage_wtn1024(wt, Wh1, tid);
        __syncthreads();

        // GEMM1 pass1: h @ Wh1a (fp32 A, non-perm)
        float acc[4][4];
#pragma unroll
        for (int nt = 0; nt < 4; nt++) {
            int cb = ncol + nt * 8 + tg * 2;
            float b0v = bh1s[cb], b1v = bh1s[cb + 1];
            acc[nt][0] = b0v; acc[nt][1] = b1v;
            acc[nt][2] = b0v; acc[nt][3] = b1v;
        }
        gemm_kloop16n(hr, wt, mrow, ncol, lane, acc);
        __syncthreads();
        stage_wtp1024(wt, Wh1 + 128 * 128, tid);
        __syncthreads();
        // GEMM1 pass2: agg @ Wh1b (perm)
        gemm_kloop16p(ap, wt, mrow, ncol, lane, acc);
        __syncthreads();

        // tt = silu(acc) -> ap (perm tf32)
#pragma unroll
        for (int rr = 0; rr < 2; rr++) {
            int row = mrow + g + rr * 8;
#pragma unroll
            for (int nt = 0; nt < 4; nt++) {
                int c = ncol + nt * 8 + tg * 2;
                int base = row * SP + (c & ~7);
                int j = c & 7;
                ap[base + (j & 3) * 2 + (j >> 2)] =
                    __uint_as_float(f2tf(siluf(acc[nt][rr * 2 + 0])));
                ap[base + ((j + 1) & 3) * 2 + ((j + 1) >> 2)] =
                    __uint_as_float(f2tf(siluf(acc[nt][rr * 2 + 1])));
            }
        }
        stage_wtp1024(wt, Wh2, tid);
        __syncthreads();

        // GEMM2: dh = tt @ Wh2 + bh2 ; v = h + dh
        float acc2[4][4];
#pragma unroll
        for (int nt = 0; nt < 4; nt++) {
            int cb = ncol + nt * 8 + tg * 2;
            float b0v = bh2s[cb], b1v = bh2s[cb + 1];
            acc2[nt][0] = b0v; acc2[nt][1] = b1v;
            acc2[nt][2] = b0v; acc2[nt][3] = b1v;
        }
        gemm_kloop16p(ap, wt, mrow, ncol, lane, acc2);

        float vsum[2] = {0.f, 0.f}, vsq[2] = {0.f, 0.f};
#pragma unroll
        for (int rr = 0; rr < 2; rr++) {
            int row = mrow + g + rr * 8;
#pragma unroll
            for (int nt = 0; nt < 4; nt++) {
                int cb = ncol + nt * 8 + tg * 2;
                float v0 = hr[row * SP + cb] + acc2[nt][rr * 2 + 0];
                float v1 = hr[row * SP + cb + 1] + acc2[nt][rr * 2 + 1];
                acc2[nt][rr * 2 + 0] = v0;
                acc2[nt][rr * 2 + 1] = v1;
                vsum[rr] += v0 + v1;
                vsq[rr] += v0 * v0 + v1 * v1;
            }
        }
#pragma unroll
        for (int i = 0; i < 2; i++) {
            vsum[i] += __shfl_xor_sync(0xffffffffu, vsum[i], 1);
            vsum[i] += __shfl_xor_sync(0xffffffffu, vsum[i], 2);
            vsq[i] += __shfl_xor_sync(0xffffffffu, vsq[i], 1);
            vsq[i] += __shfl_xor_sync(0xffffffffu, vsq[i], 2);
        }
        if (tg == 0) {
            atomicAdd(&ssum[mrow + g], vsum[0]);
            atomicAdd(&ssq[mrow + g], vsq[0]);
            atomicAdd(&ssum[mrow + g + 8], vsum[1]);
            atomicAdd(&ssq[mrow + g + 8], vsq[1]);
        }
        __syncthreads();

#pragma unroll
        for (int rr = 0; rr < 2; rr++) {
            int row = mrow + g + rr * 8;
            float mean = ssum[row] * (1.0f / 128.0f);
            float var = ssq[row] * (1.0f / 128.0f) - mean * mean;
            float rstd = rsqrtf(var + 1e-5f);
            if (n0 + row < NN) {
#pragma unroll
                for (int nt = 0; nt < 4; nt++) {
                    int cb = ncol + nt * 8 + tg * 2;
                    *(float2*)&outh[(n0 + row) * 128 + cb] = make_float2(
                        (acc2[nt][rr * 2 + 0] - mean) * rstd * lngs[cb] + lnbs[cb],
                        (acc2[nt][rr * 2 + 1] - mean) * rstd * lngs[cb + 1] + lnbs[cb + 1]);
                }
            }
        }
        __syncthreads();
    }
}

// ---------------- launcher ---------------------------------------------------
extern "C" void kernel_launch(void* const* d_in, const int* in_sizes, int n_in,
                              void* d_out, int out_size) {
    const float* h = (const float*)d_in[0];
    const float* x = (const float*)d_in[1];
    const void* ei = d_in[2];
    const float* ea = (const float*)d_in[3];
    const float* We1 = (const float*)d_in[4];
    const float* be1 = (const float*)d_in[5];
    const float* We2 = (const float*)d_in[6];
    const float* be2 = (const float*)d_in[7];
    const float* Wh1 = (const float*)d_in[8];
    const float* bh1 = (const float*)d_in[9];
    const float* Wh2 = (const float*)d_in[10];
    const float* bh2 = (const float*)d_in[11];
    const float* Wx1 = (const float*)d_in[12];
    const float* bx1 = (const float*)d_in[13];
    const float* Wx2 = (const float*)d_in[14];
    const float* bx2 = (const float*)d_in[15];
    const float* lng = (const float*)d_in[16];
    const float* lnb = (const float*)d_in[17];

    float* outh = (float*)d_out;
    float* outx = outh + (size_t)NN * 128;

    const int SMEM_EDGE = (3 * 128 * SP + 128 * 20 + 128 * 16 + 5 * 128 + 256) * 4;  // 230912
    const int SMEM_PRE = (3 * 128 * SP) * 4;                                          // 208896
    const int SMEM_UPD = (3 * 128 * SP + 6 * 128) * 4;                                // 211968
    cudaFuncSetAttribute(k_edge, cudaFuncAttributeMaxDynamicSharedMemorySize, SMEM_EDGE);
    cudaFuncSetAttribute(k_node_pre, cudaFuncAttributeMaxDynamicSharedMemorySize, SMEM_PRE);
    cudaFuncSetAttribute(k_node_upd, cudaFuncAttributeMaxDynamicSharedMemorySize, SMEM_UPD);

    k_detect<<<1, 32>>>(ei);
    k_convert<<<(EE + 255) / 256, 256>>>(ei);
    k_init<<<1024, 256>>>(x, outx);
    k_node_pre<<<PGRID, 1024, SMEM_PRE>>>(h, We1);
    k_edge<<<PGRID, 512, SMEM_EDGE>>>(x, ea, We1, be1, We2, be2, Wx1, bx1, Wx2,
                                      bx2, outx);
    k_node_upd<<<PGRID, 1024, SMEM_UPD>>>(h, Wh1, bh1, Wh2, bh2, lng, lnb, outh);
}

// round 10
// speedup vs baseline: 1.6420x; 1.2876x over previous
#include <cuda_runtime.h>
#include <cuda_fp16.h>

#define NN 50000
#define EE 800000
#define SP 136
#define SPH 72   // half2 (32-bit words) per row of fp16 tiles, padded
#define NTILE_E (EE / 128)
#define NTILE_N ((NN + 127) / 128)
#define PGRID 148

// ---------------- scratch (device globals) ----------------------------------
__device__ int   g_is64;
__device__ int   g_src[EE];
__device__ int   g_dst[EE];
__device__ float g_A[NN * 128];    // h @ We1[0:128]
__device__ float g_B[NN * 128];    // h @ We1[128:256]
__device__ float g_agg[NN * 128];  // segment-sum of m

__device__ __forceinline__ float siluf(float v) {
    float t;
    asm("tanh.approx.f32 %0, %1;" : "=f"(t) : "f"(0.5f * v));
    return 0.5f * v * (1.0f + t);
}

__device__ __forceinline__ unsigned f2tf(float v) {
    unsigned u;
    asm("cvt.rna.tf32.f32 %0, %1;" : "=r"(u) : "f"(v));
    return u;
}

// permuted slot of k within its 8-group (tf32 path): pairs (t, t+4) adjacent
__device__ __forceinline__ int kpos(int k) {
    return (k & ~7) + ((k & 3) * 2 + ((k >> 2) & 1));
}

// permuted slot of half2 index j within its 8-half2 (16-k) group:
// pairs (t, t+4) adjacent so one 64-bit LDS yields (k2t pair, k2t+8 pair)
__device__ __forceinline__ int hslot(int j) {
    return (j & ~7) + ((j & 3) * 2 + ((j >> 2) & 1));
}

__device__ __forceinline__ unsigned pack_h2(float a, float b) {
    __half2 h = __floats2half2_rn(a, b);
    return *(unsigned*)&h;
}

__device__ __forceinline__ void mma8(float* c, const unsigned* a, const unsigned* b) {
    asm volatile(
        "mma.sync.aligned.m16n8k8.row.col.f32.tf32.tf32.f32 "
        "{%0,%1,%2,%3},{%4,%5,%6,%7},{%8,%9},{%0,%1,%2,%3};"
        : "+f"(c[0]), "+f"(c[1]), "+f"(c[2]), "+f"(c[3])
        : "r"(a[0]), "r"(a[1]), "r"(a[2]), "r"(a[3]), "r"(b[0]), "r"(b[1]));
}

__device__ __forceinline__ void mma16h(float* c, const unsigned* a, const unsigned* b) {
    asm volatile(
        "mma.sync.aligned.m16n8k16.row.col.f32.f16.f16.f32 "
        "{%0,%1,%2,%3},{%4,%5,%6,%7},{%8,%9},{%0,%1,%2,%3};"
        : "+f"(c[0]), "+f"(c[1]), "+f"(c[2]), "+f"(c[3])
        : "r"(a[0]), "r"(a[1]), "r"(a[2]), "r"(a[3]), "r"(b[0]), "r"(b[1]));
}

// ---- stage weight 128x128 row-major -> WT[n][kpos(k)] tf32 (node kernels) --
__device__ __forceinline__ void stage_wtp1024(float* wt, const float* __restrict__ W,
                                              int tid) {
#pragma unroll
    for (int s = 0; s < 16; s++) {
        int i = s * 1024 + tid;
        int n = i & 127, k = i >> 7;
        wt[n * SP + kpos(k)] = __uint_as_float(f2tf(W[k * 128 + n]));
    }
}

// non-permuted staging (for fp32-A pass, 1024 thr)
__device__ __forceinline__ void stage_wtn1024(float* wt, const float* __restrict__ W,
                                              int tid) {
#pragma unroll
    for (int s = 0; s < 16; s++) {
        int i = s * 1024 + tid;
        int n = i & 127, k = i >> 7;
        wt[n * SP + k] = __uint_as_float(f2tf(W[k * 128 + n]));
    }
}

// ---- stage weight 128x128 -> half2 WT[n][hslot(j)] (edge kernel, 512 thr) --
__device__ __forceinline__ void stage_wth512(unsigned* wt, const float* __restrict__ W,
                                             int tid) {
#pragma unroll
    for (int s = 0; s < 16; s++) {
        int i = s * 512 + tid;
        int n = i & 127, j = i >> 7;  // j = half2 index 0..63
        float w0 = W[(2 * j) * 128 + n];
        float w1 = W[(2 * j + 1) * 128 + n];
        wt[n * SPH + hslot(j)] = pack_h2(w0, w1);
    }
}

// ---- tf32 k-loop: M=16, N=32, K=128 (node kernels) ------------------------
__device__ __forceinline__ void gemm_kloop16p(const float* sA, const float* wt,
                                              int mrow, int ncol, int lane,
                                              float acc[4][4]) {
    int g = lane >> 2, tg = lane & 3;
    const float* ap0 = sA + (mrow + g) * SP + 2 * tg;
    const float* ap1 = ap0 + 8 * SP;
    const float* bp0 = wt + (ncol + g) * SP + 2 * tg;
#pragma unroll
    for (int kk = 0; kk < 16; kk++) {
        int k0 = kk * 8;
        float2 a02 = *(const float2*)(ap0 + k0);
        float2 a13 = *(const float2*)(ap1 + k0);
        unsigned a[4] = {__float_as_uint(a02.x), __float_as_uint(a13.x),
                         __float_as_uint(a02.y), __float_as_uint(a13.y)};
#pragma unroll
        for (int nt = 0; nt < 4; nt++) {
            float2 b = *(const float2*)(bp0 + nt * 8 * SP + k0);
            unsigned bb[2] = {__float_as_uint(b.x), __float_as_uint(b.y)};
            mma8(acc[nt], a, bb);
        }
    }
}

// ---- fp16 k-loop: M=32, N=32, K=128 (edge kernel) -------------------------
__device__ __forceinline__ void gemm_kloop32h(const unsigned* sA, const unsigned* wt,
                                              int mrow, int ncol, int lane,
                                              float accA[4][4], float accB[4][4]) {
    int g = lane >> 2, tg = lane & 3;
    const unsigned* a0 = sA + (mrow + g) * SPH + 2 * tg;
    const unsigned* b0 = wt + (ncol + g) * SPH + 2 * tg;
#pragma unroll
    for (int kk = 0; kk < 8; kk++) {
        int k0 = kk * 8;
        uint2 r0 = *(const uint2*)(a0 + k0);
        uint2 r1 = *(const uint2*)(a0 + 8 * SPH + k0);
        uint2 r2 = *(const uint2*)(a0 + 16 * SPH + k0);
        uint2 r3 = *(const uint2*)(a0 + 24 * SPH + k0);
        unsigned aA[4] = {r0.x, r1.x, r0.y, r1.y};
        unsigned aB[4] = {r2.x, r3.x, r2.y, r3.y};
#pragma unroll
        for (int nt = 0; nt < 4; nt++) {
            uint2 bv = *(const uint2*)(b0 + nt * 8 * SPH + k0);
            unsigned bb[2] = {bv.x, bv.y};
            mma16h(accA[nt], aA, bb);
            mma16h(accB[nt], aB, bb);
        }
    }
}

// ---- fp32-A non-perm k-loop: M=16, N=32, K=128 (node_upd pass1) -----------
__device__ __forceinline__ void gemm_kloop16n(const float* sA, const float* wt,
                                              int mrow, int ncol, int lane,
                                              float acc[4][4]) {
    int g = lane >> 2, tg = lane & 3;
    const float* a0p = sA + (mrow + g) * SP + tg;
    const float* b0p = wt + (ncol + g) * SP + tg;
#pragma unroll
    for (int kk = 0; kk < 16; kk++) {
        int k0 = kk * 8;
        unsigned a[4];
        a[0] = f2tf(a0p[k0]);
        a[1] = f2tf(a0p[8 * SP + k0]);
        a[2] = f2tf(a0p[k0 + 4]);
        a[3] = f2tf(a0p[8 * SP + k0 + 4]);
#pragma unroll
        for (int nt = 0; nt < 4; nt++) {
            const float* bp = b0p + nt * 8 * SP + k0;
            unsigned b[2] = {__float_as_uint(bp[0]), __float_as_uint(bp[4])};
            mma8(acc[nt], a, b);
        }
    }
}

// ---------------- index dtype detection + conversion ------------------------
__global__ void k_detect(const void* ei) {
    if (blockIdx.x == 0 && threadIdx.x == 0) {
        const int* p = (const int*)ei;
        int acc = 0;
        for (int i = 0; i < 64; i++) acc |= p[2 * i + 1];
        g_is64 = (acc == 0) ? 1 : 0;
    }
}

__global__ void k_convert(const void* ei) {
    int e = blockIdx.x * blockDim.x + threadIdx.x;
    if (e >= EE) return;
    if (g_is64) {
        const long long* p = (const long long*)ei;
        g_src[e] = (int)p[e];
        g_dst[e] = (int)p[EE + e];
    } else {
        const int* p = (const int*)ei;
        g_src[e] = p[e];
        g_dst[e] = p[EE + e];
    }
}

// ---------------- init: zero agg, x_out = x ---------------------------------
__global__ void k_init(const float* __restrict__ x, float* __restrict__ outx) {
    for (int i = blockIdx.x * blockDim.x + threadIdx.x; i < NN * 128;
         i += gridDim.x * blockDim.x) {
        g_agg[i] = 0.0f;
        if (i < NN * 3) outx[i] = x[i];
    }
}

// ---------------- node pre-GEMM (persistent, 1024 thr, tf32) ----------------
__global__ __launch_bounds__(1024, 1) void k_node_pre(
    const float* __restrict__ h, const float* __restrict__ We1) {
    extern __shared__ float sm[];
    float* ht = sm;               // 128*SP perm tf32
    float* wtA = ht + 128 * SP;
    float* wtB = wtA + 128 * SP;

    int tid = threadIdx.x, lane = tid & 31, warp = tid >> 5;
    stage_wtp1024(wtA, We1, tid);
    stage_wtp1024(wtB, We1 + 128 * 128, tid);
    __syncthreads();

    int mrow = (warp >> 2) * 16, ncol = (warp & 3) * 32;
    int g = lane >> 2, tg = lane & 3;

    for (int t = blockIdx.x; t < NTILE_N; t += gridDim.x) {
        int n0 = t * 128;
#pragma unroll
        for (int v = 0; v < 4; v++) {
            int f = v * 1024 + tid;
            int r = f >> 5, c4 = (f & 31) * 4;
            float4 val = make_float4(0.f, 0.f, 0.f, 0.f);
            if (n0 + r < NN) val = *(const float4*)&h[(n0 + r) * 128 + c4];
            int base = r * SP + (c4 & ~7);
            int off = (c4 & 7) >> 2;
            ht[base + 0 + off] = __uint_as_float(f2tf(val.x));
            ht[base + 2 + off] = __uint_as_float(f2tf(val.y));
            ht[base + 4 + off] = __uint_as_float(f2tf(val.z));
            ht[base + 6 + off] = __uint_as_float(f2tf(val.w));
        }
        __syncthreads();
#pragma unroll
        for (int half = 0; half < 2; half++) {
            float acc[4][4];
#pragma unroll
            for (int nt = 0; nt < 4; nt++)
#pragma unroll
                for (int l = 0; l < 4; l++) acc[nt][l] = 0.f;
            gemm_kloop16p(ht, half ? wtB : wtA, mrow, ncol, lane, acc);
            float* out = half ? g_B : g_A;
#pragma unroll
            for (int nt = 0; nt < 4; nt++) {
                int r = mrow + g;
                int cb = ncol + nt * 8 + tg * 2;
                if (n0 + r < NN)
                    *(float2*)&out[(n0 + r) * 128 + cb] = make_float2(acc[nt][0], acc[nt][1]);
                if (n0 + r + 8 < NN)
                    *(float2*)&out[(n0 + r + 8) * 128 + cb] = make_float2(acc[nt][2], acc[nt][3]);
            }
        }
        __syncthreads();
    }
}

// ---------------- fused edge kernel (persistent, 512 thr, fp16 GEMMs) -------
__global__ __launch_bounds__(512, 1) void k_edge(
    const float* __restrict__ x, const float* __restrict__ ea,
    const float* __restrict__ We1, const float* __restrict__ be1,
    const float* __restrict__ We2, const float* __restrict__ be2,
    const float* __restrict__ Wx1, const float* __restrict__ bx1,
    const float* __restrict__ Wx2, const float* __restrict__ bx2,
    float* __restrict__ outx) {
    extern __shared__ float sm[];
    unsigned* tileh = (unsigned*)sm;        // 128*SPH half2 (s -> mm)
    unsigned* wt2h = tileh + 128 * SPH;     // We2^T fp16 perm
    unsigned* wtxh = wt2h + 128 * SPH;      // Wx1^T fp16 perm
    float* sEA = (float*)(wtxh + 128 * SPH);  // 128*20: ea[16]|dist|si|di|pad
    float* wtE = sEA + 128 * 20;            // 128*16: edge-attr block, tf32 perm
    float* wds = wtE + 128 * 16;
    float* be1s = wds + 128;
    float* be2s = be1s + 128;
    float* bx1s = be2s + 128;
    float* wx2s = bx1s + 128;
    float* sgate = wx2s + 128;              // 2*128 (double-buffered)

    int tid = threadIdx.x, lane = tid & 31, warp = tid >> 5;

    // ---- one-time staging ----
    stage_wth512(wt2h, We2, tid);
    stage_wth512(wtxh, Wx1, tid);
#pragma unroll
    for (int s = 0; s < 4; s++) {
        int i = s * 512 + tid;
        int n = i & 127, k = i >> 7;
        wtE[n * 16 + kpos(k)] = __uint_as_float(f2tf(We1[(256 + k) * 128 + n]));
    }
    if (tid < 128) {
        wds[tid] = We1[272 * 128 + tid];
        be1s[tid] = be1[tid];
        be2s[tid] = be2[tid];
        bx1s[tid] = bx1[tid];
        wx2s[tid] = Wx2[tid];
    }
    float bx2v = bx2[0];

    // warp tile: M=32, N=32
    int mrow = (warp & 3) * 32, ncol = (warp >> 2) * 32;
    int g = lane >> 2, tg = lane & 3;
    int e_l = tid >> 2, q = tid & 3;

    // ---- stage first tile ----
    {
        int e = blockIdx.x * 128 + e_l;
        *(float4*)&sEA[e_l * 20 + q * 4] = *(const float4*)&ea[e * 16 + q * 4];
        if (q == 0) {
            int si = g_src[e], di = g_dst[e];
            float dx = x[di * 3 + 0] - x[si * 3 + 0];
            float dy = x[di * 3 + 1] - x[si * 3 + 1];
            float dz = x[di * 3 + 2] - x[si * 3 + 2];
            sEA[e_l * 20 + 16] = sqrtf(dx * dx + dy * dy + dz * dz + 1e-9f);
            ((int*)sEA)[e_l * 20 + 17] = si;
            ((int*)sEA)[e_l * 20 + 18] = di;
        }
        if (tid < 128) sgate[tid] = bx2v;
    }
    __syncthreads();

    int pb = 0;
    for (int t = blockIdx.x; t < NTILE_E; t += PGRID) {
        float* sg_cur = sgate + pb * 128;
        float* sg_nxt = sgate + (pb ^ 1) * 128;
        int tn = t + PGRID;
        bool hn = tn < NTILE_E;

        // ---- ea-GEMM (K=16, M=32, tf32) + fused gather + silu -> tileh -----
        {
            float accA[4][4], accB[4][4];
#pragma unroll
            for (int nt = 0; nt < 4; nt++)
#pragma unroll
                for (int l = 0; l < 4; l++) { accA[nt][l] = 0.f; accB[nt][l] = 0.f; }
            const float* a0p = sEA + (mrow + g) * 20 + tg;
            const float* b0p = wtE + (ncol + g) * 16 + 2 * tg;
#pragma unroll
            for (int kk = 0; kk < 2; kk++) {
                int k0 = kk * 8;
                unsigned aA[4], aB[4];
                aA[0] = f2tf(a0p[k0]);
                aA[1] = f2tf(a0p[8 * 20 + k0]);
                aA[2] = f2tf(a0p[k0 + 4]);
                aA[3] = f2tf(a0p[8 * 20 + k0 + 4]);
                aB[0] = f2tf(a0p[16 * 20 + k0]);
                aB[1] = f2tf(a0p[24 * 20 + k0]);
                aB[2] = f2tf(a0p[16 * 20 + k0 + 4]);
                aB[3] = f2tf(a0p[24 * 20 + k0 + 4]);
#pragma unroll
                for (int nt = 0; nt < 4; nt++) {
                    float2 b = *(const float2*)(b0p + nt * 8 * 16 + k0);
                    unsigned bb[2] = {__float_as_uint(b.x), __float_as_uint(b.y)};
                    mma8(accA[nt], aA, bb);
                    mma8(accB[nt], aB, bb);
                }
            }
#pragma unroll
            for (int rr = 0; rr < 4; rr++) {
                int row = mrow + g + rr * 8;
                float* ac = (rr < 2) ? &accA[0][0] : &accB[0][0];
                int jo = (rr & 1) * 2;
                int si = ((const int*)sEA)[row * 20 + 17];
                int di = ((const int*)sEA)[row * 20 + 18];
                float dist = sEA[row * 20 + 16];
#pragma unroll
                for (int nt = 0; nt < 4; nt++) {
                    int c = ncol + nt * 8 + tg * 2;
                    float2 a2 = *(const float2*)&g_A[si * 128 + c];
                    float2 b2 = *(const float2*)&g_B[di * 128 + c];
                    float v0 = ac[nt * 4 + jo + 0] + dist * wds[c] + be1s[c] + a2.x + b2.x;
                    float v1 = ac[nt * 4 + jo + 1] + dist * wds[c + 1] + be1s[c + 1] +
                               a2.y + b2.y;
                    tileh[row * SPH + hslot(c >> 1)] = pack_h2(siluf(v0), siluf(v1));
                }
            }
        }
        __syncthreads();  // A

        // ---- GEMM1 (fp16): mm = s @ We2 + be2 ----
        float accmA[4][4], accmB[4][4];
#pragma unroll
        for (int nt = 0; nt < 4; nt++) {
            int cb = ncol + nt * 8 + tg * 2;
            float b0v = be2s[cb], b1v = be2s[cb + 1];
            accmA[nt][0] = b0v; accmA[nt][1] = b1v;
            accmA[nt][2] = b0v; accmA[nt][3] = b1v;
            accmB[nt][0] = b0v; accmB[nt][1] = b1v;
            accmB[nt][2] = b0v; accmB[nt][3] = b1v;
        }
        gemm_kloop32h(tileh, wt2h, mrow, ncol, lane, accmA, accmB);

        // agg scatter: pair-merge via shfl -> red.v4 (half the ops)
#pragma unroll
        for (int rr = 0; rr < 4; rr++) {
            int row = mrow + g + rr * 8;
            const float* ac = (rr < 2) ? &accmA[0][0] : &accmB[0][0];
            int jo = (rr & 1) * 2;
            int di = ((const int*)sEA)[row * 20 + 18];
#pragma unroll
            for (int nt = 0; nt < 4; nt++) {
                float v0 = ac[nt * 4 + jo + 0];
                float v1 = ac[nt * 4 + jo + 1];
                float o0 = __shfl_xor_sync(0xffffffffu, v0, 1);
                float o1 = __shfl_xor_sync(0xffffffffu, v1, 1);
                if ((tg & 1) == 0) {
                    int c = ncol + nt * 8 + tg * 2;  // tg in {0,2} -> c mult of 4
                    asm volatile("red.global.add.v4.f32 [%0], {%1,%2,%3,%4};"
                                 :: "l"(&g_agg[di * 128 + c]),
                                    "f"(v0), "f"(v1), "f"(o0), "f"(o1)
                                 : "memory");
                }
            }
        }
        __syncthreads();  // B (all warps done reading s before overwrite)

        // store mm into tileh (fp16 perm)
#pragma unroll
        for (int rr = 0; rr < 4; rr++) {
            int row = mrow + g + rr * 8;
            const float* ac = (rr < 2) ? &accmA[0][0] : &accmB[0][0];
            int jo = (rr & 1) * 2;
#pragma unroll
            for (int nt = 0; nt < 4; nt++) {
                int c = ncol + nt * 8 + tg * 2;
                tileh[row * SPH + hslot(c >> 1)] =
                    pack_h2(ac[nt * 4 + jo + 0], ac[nt * 4 + jo + 1]);
            }
        }
        __syncthreads();  // C

        // ---- prefetch next tile (regs) + snapshot scatter info ----
        float4 pea;
        int psi = 0, pdi = 0;
        float pdx = 0.f, pdy = 0.f, pdz = 0.f;
        if (hn) {
            int e = tn * 128 + e_l;
            pea = *(const float4*)&ea[e * 16 + q * 4];
            if (q == 0) {
                psi = g_src[e];
                pdi = g_dst[e];
                pdx = x[pdi * 3 + 0] - x[psi * 3 + 0];
                pdy = x[pdi * 3 + 1] - x[psi * 3 + 1];
                pdz = x[pdi * 3 + 2] - x[psi * 3 + 2];
            }
        }
        int xsi = 0, xdi = 0;
        if (tid < 128) {
            xsi = ((const int*)sEA)[tid * 20 + 17];
            xdi = ((const int*)sEA)[tid * 20 + 18];
        }

        // ---- GEMM2 (fp16): gate = sum silu(mm@Wx1+bx1)*wx2 ----
        {
            float accA[4][4], accB[4][4];
#pragma unroll
            for (int nt = 0; nt < 4; nt++) {
                int cb = ncol + nt * 8 + tg * 2;
                float b0v = bx1s[cb], b1v = bx1s[cb + 1];
                accA[nt][0] = b0v; accA[nt][1] = b1v;
                accA[nt][2] = b0v; accA[nt][3] = b1v;
                accB[nt][0] = b0v; accB[nt][1] = b1v;
                accB[nt][2] = b0v; accB[nt][3] = b1v;
            }
            gemm_kloop32h(tileh, wtxh, mrow, ncol, lane, accA, accB);
            float p[4] = {0.f, 0.f, 0.f, 0.f};
#pragma unroll
            for (int nt = 0; nt < 4; nt++) {
                int cb = ncol + nt * 8 + tg * 2;
                float w0 = wx2s[cb], w1 = wx2s[cb + 1];
                p[0] += siluf(accA[nt][0]) * w0 + siluf(accA[nt][1]) * w1;
                p[1] += siluf(accA[nt][2]) * w0 + siluf(accA[nt][3]) * w1;
                p[2] += siluf(accB[nt][0]) * w0 + siluf(accB[nt][1]) * w1;
                p[3] += siluf(accB[nt][2]) * w0 + siluf(accB[nt][3]) * w1;
            }
#pragma unroll
            for (int i = 0; i < 4; i++) {
                p[i] += __shfl_xor_sync(0xffffffffu, p[i], 1);
                p[i] += __shfl_xor_sync(0xffffffffu, p[i], 2);
            }
            if (tg == 0) {
                atomicAdd(&sg_cur[mrow + g], p[0]);
                atomicAdd(&sg_cur[mrow + g + 8], p[1]);
                atomicAdd(&sg_cur[mrow + g + 16], p[2]);
                atomicAdd(&sg_cur[mrow + g + 24], p[3]);
            }
        }
        __syncthreads();  // D

        // ---- x scatter (snapshotted indices) + stage next tile ----
        if (tid < 128) {
            float dx = x[xdi * 3 + 0] - x[xsi * 3 + 0];
            float dy = x[xdi * 3 + 1] - x[xsi * 3 + 1];
            float dz = x[xdi * 3 + 2] - x[xsi * 3 + 2];
            float rn = __fdividef(1.0f, sqrtf(dx * dx + dy * dy + dz * dz) + 1e-9f);
            float gte = sg_cur[tid];
            atomicAdd(&outx[xdi * 3 + 0], dx * rn * gte);
            atomicAdd(&outx[xdi * 3 + 1], dy * rn * gte);
            atomicAdd(&outx[xdi * 3 + 2], dz * rn * gte);
            sg_nxt[tid] = bx2v;
        }
        if (hn) {
            *(float4*)&sEA[e_l * 20 + q * 4] = pea;
            if (q == 0) {
                sEA[e_l * 20 + 16] = sqrtf(pdx * pdx + pdy * pdy + pdz * pdz + 1e-9f);
                ((int*)sEA)[e_l * 20 + 17] = psi;
                ((int*)sEA)[e_l * 20 + 18] = pdi;
            }
        }
        __syncthreads();  // E
        pb ^= 1;
    }
}

// ---------------- node update (persistent, 1024 thr, tf32) ------------------
__global__ __launch_bounds__(1024, 1) void k_node_upd(
    const float* __restrict__ h, const float* __restrict__ Wh1,
    const float* __restrict__ bh1, const float* __restrict__ Wh2,
    const float* __restrict__ bh2, const float* __restrict__ lng,
    const float* __restrict__ lnb, float* __restrict__ outh) {
    extern __shared__ float sm[];
    float* hr = sm;              // 128*SP fp32 row-major
    float* ap = hr + 128 * SP;   // 128*SP perm tf32 (agg, then tt)
    float* wt = ap + 128 * SP;
    float* bh1s = wt + 128 * SP;
    float* bh2s = bh1s + 128;
    float* lngs = bh2s + 128;
    float* lnbs = lngs + 128;
    float* ssum = lnbs + 128;
    float* ssq = ssum + 128;

    int tid = threadIdx.x, lane = tid & 31, warp = tid >> 5;
    if (tid < 128) {
        bh1s[tid] = bh1[tid];
        bh2s[tid] = bh2[tid];
        lngs[tid] = lng[tid];
        lnbs[tid] = lnb[tid];
    }

    int mrow = (warp >> 2) * 16, ncol = (warp & 3) * 32;
    int g = lane >> 2, tg = lane & 3;

    for (int t = blockIdx.x; t < NTILE_N; t += gridDim.x) {
        int n0 = t * 128;
        if (tid < 128) {
            ssum[tid] = 0.f;
            ssq[tid] = 0.f;
        }
#pragma unroll
        for (int v = 0; v < 4; v++) {
            int f = v * 1024 + tid;
            int r = f >> 5, c4 = (f & 31) * 4;
            float4 hv = make_float4(0.f, 0.f, 0.f, 0.f);
            float4 av = make_float4(0.f, 0.f, 0.f, 0.f);
            if (n0 + r < NN) {
                hv = *(const float4*)&h[(n0 + r) * 128 + c4];
                av = *(const float4*)&g_agg[(n0 + r) * 128 + c4];
            }
            *(float4*)&hr[r * SP + c4] = hv;
            int base = r * SP + (c4 & ~7);
            int off = (c4 & 7) >> 2;
            ap[base + 0 + off] = __uint_as_float(f2tf(av.x));
            ap[base + 2 + off] = __uint_as_float(f2tf(av.y));
            ap[base + 4 + off] = __uint_as_float(f2tf(av.z));
            ap[base + 6 + off] = __uint_as_float(f2tf(av.w));
        }
        stage_wtn1024(wt, Wh1, tid);
        __syncthreads();

        float acc[4][4];
#pragma unroll
        for (int nt = 0; nt < 4; nt++) {
            int cb = ncol + nt * 8 + tg * 2;
            float b0v = bh1s[cb], b1v = bh1s[cb + 1];
            acc[nt][0] = b0v; acc[nt][1] = b1v;
            acc[nt][2] = b0v; acc[nt][3] = b1v;
        }
        gemm_kloop16n(hr, wt, mrow, ncol, lane, acc);
        __syncthreads();
        stage_wtp1024(wt, Wh1 + 128 * 128, tid);
        __syncthreads();
        gemm_kloop16p(ap, wt, mrow, ncol, lane, acc);
        __syncthreads();

#pragma unroll
        for (int rr = 0; rr < 2; rr++) {
            int row = mrow + g + rr * 8;
#pragma unroll
            for (int nt = 0; nt < 4; nt++) {
                int c = ncol + nt * 8 + tg * 2;
                int base = row * SP + (c & ~7);
                int j = c & 7;
                ap[base + (j & 3) * 2 + (j >> 2)] =
                    __uint_as_float(f2tf(siluf(acc[nt][rr * 2 + 0])));
                ap[base + ((j + 1) & 3) * 2 + ((j + 1) >> 2)] =
                    __uint_as_float(f2tf(siluf(acc[nt][rr * 2 + 1])));
            }
        }
        stage_wtp1024(wt, Wh2, tid);
        __syncthreads();

        float acc2[4][4];
#pragma unroll
        for (int nt = 0; nt < 4; nt++) {
            int cb = ncol + nt * 8 + tg * 2;
            float b0v = bh2s[cb], b1v = bh2s[cb + 1];
            acc2[nt][0] = b0v; acc2[nt][1] = b1v;
            acc2[nt][2] = b0v; acc2[nt][3] = b1v;
        }
        gemm_kloop16p(ap, wt, mrow, ncol, lane, acc2);

        float vsum[2] = {0.f, 0.f}, vsq[2] = {0.f, 0.f};
#pragma unroll
        for (int rr = 0; rr < 2; rr++) {
            int row = mrow + g + rr * 8;
#pragma unroll
            for (int nt = 0; nt < 4; nt++) {
                int cb = ncol + nt * 8 + tg * 2;
                float v0 = hr[row * SP + cb] + acc2[nt][rr * 2 + 0];
                float v1 = hr[row * SP + cb + 1] + acc2[nt][rr * 2 + 1];
                acc2[nt][rr * 2 + 0] = v0;
                acc2[nt][rr * 2 + 1] = v1;
                vsum[rr] += v0 + v1;
                vsq[rr] += v0 * v0 + v1 * v1;
            }
        }
#pragma unroll
        for (int i = 0; i < 2; i++) {
            vsum[i] += __shfl_xor_sync(0xffffffffu, vsum[i], 1);
            vsum[i] += __shfl_xor_sync(0xffffffffu, vsum[i], 2);
            vsq[i] += __shfl_xor_sync(0xffffffffu, vsq[i], 1);
            vsq[i] += __shfl_xor_sync(0xffffffffu, vsq[i], 2);
        }
        if (tg == 0) {
            atomicAdd(&ssum[mrow + g], vsum[0]);
            atomicAdd(&ssq[mrow + g], vsq[0]);
            atomicAdd(&ssum[mrow + g + 8], vsum[1]);
            atomicAdd(&ssq[mrow + g + 8], vsq[1]);
        }
        __syncthreads();

#pragma unroll
        for (int rr = 0; rr < 2; rr++) {
            int row = mrow + g + rr * 8;
            float mean = ssum[row] * (1.0f / 128.0f);
            float var = ssq[row] * (1.0f / 128.0f) - mean * mean;
            float rstd = rsqrtf(var + 1e-5f);
            if (n0 + row < NN) {
#pragma unroll
                for (int nt = 0; nt < 4; nt++) {
                    int cb = ncol + nt * 8 + tg * 2;
                    *(float2*)&outh[(n0 + row) * 128 + cb] = make_float2(
                        (acc2[nt][rr * 2 + 0] - mean) * rstd * lngs[cb] + lnbs[cb],
                        (acc2[nt][rr * 2 + 1] - mean) * rstd * lngs[cb + 1] + lnbs[cb + 1]);
                }
            }
        }
        __syncthreads();
    }
}

// ---------------- launcher ---------------------------------------------------
extern "C" void kernel_launch(void* const* d_in, const int* in_sizes, int n_in,
                              void* d_out, int out_size) {
    const float* h = (const float*)d_in[0];
    const float* x = (const float*)d_in[1];
    const void* ei = d_in[2];
    const float* ea = (const float*)d_in[3];
    const float* We1 = (const float*)d_in[4];
    const float* be1 = (const float*)d_in[5];
    const float* We2 = (const float*)d_in[6];
    const float* be2 = (const float*)d_in[7];
    const float* Wh1 = (const float*)d_in[8];
    const float* bh1 = (const float*)d_in[9];
    const float* Wh2 = (const float*)d_in[10];
    const float* bh2 = (const float*)d_in[11];
    const float* Wx1 = (const float*)d_in[12];
    const float* bx1 = (const float*)d_in[13];
    const float* Wx2 = (const float*)d_in[14];
    const float* bx2 = (const float*)d_in[15];
    const float* lng = (const float*)d_in[16];
    const float* lnb = (const float*)d_in[17];

    float* outh = (float*)d_out;
    float* outx = outh + (size_t)NN * 128;

    const int SMEM_EDGE = (3 * 128 * SPH + 128 * 20 + 128 * 16 + 5 * 128 + 256) * 4;  // 132608
    const int SMEM_PRE = (3 * 128 * SP) * 4;                                           // 208896
    const int SMEM_UPD = (3 * 128 * SP + 6 * 128) * 4;                                 // 211968
    cudaFuncSetAttribute(k_edge, cudaFuncAttributeMaxDynamicSharedMemorySize, SMEM_EDGE);
    cudaFuncSetAttribute(k_node_pre, cudaFuncAttributeMaxDynamicSharedMemorySize, SMEM_PRE);
    cudaFuncSetAttribute(k_node_upd, cudaFuncAttributeMaxDynamicSharedMemorySize, SMEM_UPD);

    k_detect<<<1, 32>>>(ei);
    k_convert<<<(EE + 255) / 256, 256>>>(ei);
    k_init<<<1024, 256>>>(x, outx);
    k_node_pre<<<PGRID, 1024, SMEM_PRE>>>(h, We1);
    k_edge<<<PGRID, 512, SMEM_EDGE>>>(x, ea, We1, be1, We2, be2, Wx1, bx1, Wx2,
                                      bx2, outx);
    k_node_upd<<<PGRID, 1024, SMEM_UPD>>>(h, Wh1, bh1, Wh2, bh2, lng, lnb, outh);
}

// round 11
// speedup vs baseline: 1.6971x; 1.0336x over previous
#include <cuda_runtime.h>
#include <cuda_fp16.h>

#define NN 50000
#define EE 800000
#define SP 136
#define SPH 72   // half2 (32-bit words) per row of fp16 tiles, padded
#define NTILE_E (EE / 128)
#define NTILE_N ((NN + 127) / 128)
#define PGRID 148

// ---------------- scratch (device globals) ----------------------------------
__device__ int      g_is64;
__device__ int      g_src[EE];
__device__ int      g_dst[EE];
__device__ unsigned g_Ah[NN * 64];   // h @ We1[0:128], half2-packed
__device__ unsigned g_Bh[NN * 64];   // h @ We1[128:256], half2-packed
__device__ float    g_agg[NN * 128]; // segment-sum of m (fp32)

__device__ __forceinline__ float siluf(float v) {
    float t;
    asm("tanh.approx.f32 %0, %1;" : "=f"(t) : "f"(0.5f * v));
    return 0.5f * v * (1.0f + t);
}

__device__ __forceinline__ unsigned f2tf(float v) {
    unsigned u;
    asm("cvt.rna.tf32.f32 %0, %1;" : "=r"(u) : "f"(v));
    return u;
}

// permuted slot of k within its 8-group (tf32 path): pairs (t, t+4) adjacent
__device__ __forceinline__ int kpos(int k) {
    return (k & ~7) + ((k & 3) * 2 + ((k >> 2) & 1));
}

// permuted slot of half2 index j within its 8-half2 (16-k) group
__device__ __forceinline__ int hslot(int j) {
    return (j & ~7) + ((j & 3) * 2 + ((j >> 2) & 1));
}

__device__ __forceinline__ unsigned pack_h2(float a, float b) {
    __half2 h = __floats2half2_rn(a, b);
    return *(unsigned*)&h;
}

__device__ __forceinline__ float2 unpack_h2(unsigned u) {
    __half2 h = *(__half2*)&u;
    return __half22float2(h);
}

__device__ __forceinline__ void mma8(float* c, const unsigned* a, const unsigned* b) {
    asm volatile(
        "mma.sync.aligned.m16n8k8.row.col.f32.tf32.tf32.f32 "
        "{%0,%1,%2,%3},{%4,%5,%6,%7},{%8,%9},{%0,%1,%2,%3};"
        : "+f"(c[0]), "+f"(c[1]), "+f"(c[2]), "+f"(c[3])
        : "r"(a[0]), "r"(a[1]), "r"(a[2]), "r"(a[3]), "r"(b[0]), "r"(b[1]));
}

__device__ __forceinline__ void mma16h(float* c, const unsigned* a, const unsigned* b) {
    asm volatile(
        "mma.sync.aligned.m16n8k16.row.col.f32.f16.f16.f32 "
        "{%0,%1,%2,%3},{%4,%5,%6,%7},{%8,%9},{%0,%1,%2,%3};"
        : "+f"(c[0]), "+f"(c[1]), "+f"(c[2]), "+f"(c[3])
        : "r"(a[0]), "r"(a[1]), "r"(a[2]), "r"(a[3]), "r"(b[0]), "r"(b[1]));
}

// ---- stage weight 128x128 row-major -> WT[n][kpos(k)] tf32 (node kernels) --
__device__ __forceinline__ void stage_wtp1024(float* wt, const float* __restrict__ W,
                                              int tid) {
#pragma unroll
    for (int s = 0; s < 16; s++) {
        int i = s * 1024 + tid;
        int n = i & 127, k = i >> 7;
        wt[n * SP + kpos(k)] = __uint_as_float(f2tf(W[k * 128 + n]));
    }
}

// non-permuted staging (for fp32-A pass, 1024 thr)
__device__ __forceinline__ void stage_wtn1024(float* wt, const float* __restrict__ W,
                                              int tid) {
#pragma unroll
    for (int s = 0; s < 16; s++) {
        int i = s * 1024 + tid;
        int n = i & 127, k = i >> 7;
        wt[n * SP + k] = __uint_as_float(f2tf(W[k * 128 + n]));
    }
}

// ---- stage weight 128x128 -> half2 WT[n][hslot(j)] (edge kernel, 512 thr) --
__device__ __forceinline__ void stage_wth512(unsigned* wt, const float* __restrict__ W,
                                             int tid) {
#pragma unroll
    for (int s = 0; s < 16; s++) {
        int i = s * 512 + tid;
        int n = i & 127, j = i >> 7;  // j = half2 index 0..63
        float w0 = W[(2 * j) * 128 + n];
        float w1 = W[(2 * j + 1) * 128 + n];
        wt[n * SPH + hslot(j)] = pack_h2(w0, w1);
    }
}

// ---- tf32 k-loop: M=16, N=32, K=128 (node kernels) ------------------------
__device__ __forceinline__ void gemm_kloop16p(const float* sA, const float* wt,
                                              int mrow, int ncol, int lane,
                                              float acc[4][4]) {
    int g = lane >> 2, tg = lane & 3;
    const float* ap0 = sA + (mrow + g) * SP + 2 * tg;
    const float* ap1 = ap0 + 8 * SP;
    const float* bp0 = wt + (ncol + g) * SP + 2 * tg;
#pragma unroll
    for (int kk = 0; kk < 16; kk++) {
        int k0 = kk * 8;
        float2 a02 = *(const float2*)(ap0 + k0);
        float2 a13 = *(const float2*)(ap1 + k0);
        unsigned a[4] = {__float_as_uint(a02.x), __float_as_uint(a13.x),
                         __float_as_uint(a02.y), __float_as_uint(a13.y)};
#pragma unroll
        for (int nt = 0; nt < 4; nt++) {
            float2 b = *(const float2*)(bp0 + nt * 8 * SP + k0);
            unsigned bb[2] = {__float_as_uint(b.x), __float_as_uint(b.y)};
            mma8(acc[nt], a, bb);
        }
    }
}

// ---- fp16 k-loop: M=32, N=32, K=128 (edge kernel) -------------------------
__device__ __forceinline__ void gemm_kloop32h(const unsigned* sA, const unsigned* wt,
                                              int mrow, int ncol, int lane,
                                              float accA[4][4], float accB[4][4]) {
    int g = lane >> 2, tg = lane & 3;
    const unsigned* a0 = sA + (mrow + g) * SPH + 2 * tg;
    const unsigned* b0 = wt + (ncol + g) * SPH + 2 * tg;
#pragma unroll
    for (int kk = 0; kk < 8; kk++) {
        int k0 = kk * 8;
        uint2 r0 = *(const uint2*)(a0 + k0);
        uint2 r1 = *(const uint2*)(a0 + 8 * SPH + k0);
        uint2 r2 = *(const uint2*)(a0 + 16 * SPH + k0);
        uint2 r3 = *(const uint2*)(a0 + 24 * SPH + k0);
        unsigned aA[4] = {r0.x, r1.x, r0.y, r1.y};
        unsigned aB[4] = {r2.x, r3.x, r2.y, r3.y};
#pragma unroll
        for (int nt = 0; nt < 4; nt++) {
            uint2 bv = *(const uint2*)(b0 + nt * 8 * SPH + k0);
            unsigned bb[2] = {bv.x, bv.y};
            mma16h(accA[nt], aA, bb);
            mma16h(accB[nt], aB, bb);
        }
    }
}

// ---- fp32-A non-perm k-loop: M=16, N=32, K=128 (node_upd pass1) -----------
__device__ __forceinline__ void gemm_kloop16n(const float* sA, const float* wt,
                                              int mrow, int ncol, int lane,
                                              float acc[4][4]) {
    int g = lane >> 2, tg = lane & 3;
    const float* a0p = sA + (mrow + g) * SP + tg;
    const float* b0p = wt + (ncol + g) * SP + tg;
#pragma unroll
    for (int kk = 0; kk < 16; kk++) {
        int k0 = kk * 8;
        unsigned a[4];
        a[0] = f2tf(a0p[k0]);
        a[1] = f2tf(a0p[8 * SP + k0]);
        a[2] = f2tf(a0p[k0 + 4]);
        a[3] = f2tf(a0p[8 * SP + k0 + 4]);
#pragma unroll
        for (int nt = 0; nt < 4; nt++) {
            const float* bp = b0p + nt * 8 * SP + k0;
            unsigned b[2] = {__float_as_uint(bp[0]), __float_as_uint(bp[4])};
            mma8(acc[nt], a, b);
        }
    }
}

// ---------------- index dtype detection + conversion ------------------------
__global__ void k_detect(const void* ei) {
    if (blockIdx.x == 0 && threadIdx.x == 0) {
        const int* p = (const int*)ei;
        int acc = 0;
        for (int i = 0; i < 64; i++) acc |= p[2 * i + 1];
        g_is64 = (acc == 0) ? 1 : 0;
    }
}

__global__ void k_convert(const void* ei) {
    int e = blockIdx.x * blockDim.x + threadIdx.x;
    if (e >= EE) return;
    if (g_is64) {
        const long long* p = (const long long*)ei;
        g_src[e] = (int)p[e];
        g_dst[e] = (int)p[EE + e];
    } else {
        const int* p = (const int*)ei;
        g_src[e] = p[e];
        g_dst[e] = p[EE + e];
    }
}

// ---------------- init: zero agg, x_out = x ---------------------------------
__global__ void k_init(const float* __restrict__ x, float* __restrict__ outx) {
    for (int i = blockIdx.x * blockDim.x + threadIdx.x; i < NN * 128;
         i += gridDim.x * blockDim.x) {
        g_agg[i] = 0.0f;
        if (i < NN * 3) outx[i] = x[i];
    }
}

// ---------------- node pre-GEMM (persistent, 1024 thr, tf32 -> fp16 out) ----
__global__ __launch_bounds__(1024, 1) void k_node_pre(
    const float* __restrict__ h, const float* __restrict__ We1) {
    extern __shared__ float sm[];
    float* ht = sm;               // 128*SP perm tf32
    float* wtA = ht + 128 * SP;
    float* wtB = wtA + 128 * SP;

    int tid = threadIdx.x, lane = tid & 31, warp = tid >> 5;
    stage_wtp1024(wtA, We1, tid);
    stage_wtp1024(wtB, We1 + 128 * 128, tid);
    __syncthreads();

    int mrow = (warp >> 2) * 16, ncol = (warp & 3) * 32;
    int g = lane >> 2, tg = lane & 3;

    for (int t = blockIdx.x; t < NTILE_N; t += gridDim.x) {
        int n0 = t * 128;
#pragma unroll
        for (int v = 0; v < 4; v++) {
            int f = v * 1024 + tid;
            int r = f >> 5, c4 = (f & 31) * 4;
            float4 val = make_float4(0.f, 0.f, 0.f, 0.f);
            if (n0 + r < NN) val = *(const float4*)&h[(n0 + r) * 128 + c4];
            int base = r * SP + (c4 & ~7);
            int off = (c4 & 7) >> 2;
            ht[base + 0 + off] = __uint_as_float(f2tf(val.x));
            ht[base + 2 + off] = __uint_as_float(f2tf(val.y));
            ht[base + 4 + off] = __uint_as_float(f2tf(val.z));
            ht[base + 6 + off] = __uint_as_float(f2tf(val.w));
        }
        __syncthreads();
#pragma unroll
        for (int half = 0; half < 2; half++) {
            float acc[4][4];
#pragma unroll
            for (int nt = 0; nt < 4; nt++)
#pragma unroll
                for (int l = 0; l < 4; l++) acc[nt][l] = 0.f;
            gemm_kloop16p(ht, half ? wtB : wtA, mrow, ncol, lane, acc);
            unsigned* out = half ? g_Bh : g_Ah;
#pragma unroll
            for (int nt = 0; nt < 4; nt++) {
                int r = mrow + g;
                int cb = ncol + nt * 8 + tg * 2;   // even col; half2 idx cb>>1
                if (n0 + r < NN)
                    out[(n0 + r) * 64 + (cb >> 1)] = pack_h2(acc[nt][0], acc[nt][1]);
                if (n0 + r + 8 < NN)
                    out[(n0 + r + 8) * 64 + (cb >> 1)] = pack_h2(acc[nt][2], acc[nt][3]);
            }
        }
        __syncthreads();
    }
}

// ---------------- fused edge kernel (persistent, 512 thr, fp16 GEMMs) -------
__global__ __launch_bounds__(512, 1) void k_edge(
    const float* __restrict__ x, const float* __restrict__ ea,
    const float* __restrict__ We1, const float* __restrict__ be1,
    const float* __restrict__ We2, const float* __restrict__ be2,
    const float* __restrict__ Wx1, const float* __restrict__ bx1,
    const float* __restrict__ Wx2, const float* __restrict__ bx2,
    float* __restrict__ outx) {
    extern __shared__ float sm[];
    unsigned* tileh = (unsigned*)sm;        // 128*SPH half2 (s -> mm)
    unsigned* wt2h = tileh + 128 * SPH;     // We2^T fp16 perm
    unsigned* wtxh = wt2h + 128 * SPH;      // Wx1^T fp16 perm
    float* sEA = (float*)(wtxh + 128 * SPH);  // 128*20: ea[16]|dist|si|di|pad
    float* wtE = sEA + 128 * 20;            // 128*16: edge-attr block, tf32 perm
    float* wds = wtE + 128 * 16;
    float* be1s = wds + 128;
    float* be2s = be1s + 128;
    float* bx1s = be2s + 128;
    float* wx2s = bx1s + 128;
    float* sgate = wx2s + 128;              // 2*128 (double-buffered)

    int tid = threadIdx.x, lane = tid & 31, warp = tid >> 5;

    // ---- one-time staging ----
    stage_wth512(wt2h, We2, tid);
    stage_wth512(wtxh, Wx1, tid);
#pragma unroll
    for (int s = 0; s < 4; s++) {
        int i = s * 512 + tid;
        int n = i & 127, k = i >> 7;
        wtE[n * 16 + kpos(k)] = __uint_as_float(f2tf(We1[(256 + k) * 128 + n]));
    }
    if (tid < 128) {
        wds[tid] = We1[272 * 128 + tid];
        be1s[tid] = be1[tid];
        be2s[tid] = be2[tid];
        bx1s[tid] = bx1[tid];
        wx2s[tid] = Wx2[tid];
    }
    float bx2v = bx2[0];

    // warp tile: M=32, N=32
    int mrow = (warp & 3) * 32, ncol = (warp >> 2) * 32;
    int g = lane >> 2, tg = lane & 3;
    int e_l = tid >> 2, q = tid & 3;

    // ---- stage first tile ----
    {
        int e = blockIdx.x * 128 + e_l;
        *(float4*)&sEA[e_l * 20 + q * 4] = *(const float4*)&ea[e * 16 + q * 4];
        if (q == 0) {
            int si = g_src[e], di = g_dst[e];
            float dx = x[di * 3 + 0] - x[si * 3 + 0];
            float dy = x[di * 3 + 1] - x[si * 3 + 1];
            float dz = x[di * 3 + 2] - x[si * 3 + 2];
            sEA[e_l * 20 + 16] = sqrtf(dx * dx + dy * dy + dz * dz + 1e-9f);
            ((int*)sEA)[e_l * 20 + 17] = si;
            ((int*)sEA)[e_l * 20 + 18] = di;
        }
        if (tid < 128) sgate[tid] = bx2v;
    }
    __syncthreads();

    int pb = 0;
    for (int t = blockIdx.x; t < NTILE_E; t += PGRID) {
        float* sg_cur = sgate + pb * 128;
        float* sg_nxt = sgate + (pb ^ 1) * 128;
        int tn = t + PGRID;
        bool hn = tn < NTILE_E;

        // ---- ea-GEMM (K=16, M=32, tf32) + fused fp16 gather + silu -> tileh -
        {
            float accA[4][4], accB[4][4];
#pragma unroll
            for (int nt = 0; nt < 4; nt++)
#pragma unroll
                for (int l = 0; l < 4; l++) { accA[nt][l] = 0.f; accB[nt][l] = 0.f; }
            const float* a0p = sEA + (mrow + g) * 20 + tg;
            const float* b0p = wtE + (ncol + g) * 16 + 2 * tg;
#pragma unroll
            for (int kk = 0; kk < 2; kk++) {
                int k0 = kk * 8;
                unsigned aA[4], aB[4];
                aA[0] = f2tf(a0p[k0]);
                aA[1] = f2tf(a0p[8 * 20 + k0]);
                aA[2] = f2tf(a0p[k0 + 4]);
                aA[3] = f2tf(a0p[8 * 20 + k0 + 4]);
                aB[0] = f2tf(a0p[16 * 20 + k0]);
                aB[1] = f2tf(a0p[24 * 20 + k0]);
                aB[2] = f2tf(a0p[16 * 20 + k0 + 4]);
                aB[3] = f2tf(a0p[24 * 20 + k0 + 4]);
#pragma unroll
                for (int nt = 0; nt < 4; nt++) {
                    float2 b = *(const float2*)(b0p + nt * 8 * 16 + k0);
                    unsigned bb[2] = {__float_as_uint(b.x), __float_as_uint(b.y)};
                    mma8(accA[nt], aA, bb);
                    mma8(accB[nt], aB, bb);
                }
            }
#pragma unroll
            for (int rr = 0; rr < 4; rr++) {
                int row = mrow + g + rr * 8;
                float* ac = (rr < 2) ? &accA[0][0] : &accB[0][0];
                int jo = (rr & 1) * 2;
                int si = ((const int*)sEA)[row * 20 + 17];
                int di = ((const int*)sEA)[row * 20 + 18];
                float dist = sEA[row * 20 + 16];
#pragma unroll
                for (int nt = 0; nt < 4; nt++) {
                    int c = ncol + nt * 8 + tg * 2;
                    float2 a2 = unpack_h2(g_Ah[si * 64 + (c >> 1)]);
                    float2 b2 = unpack_h2(g_Bh[di * 64 + (c >> 1)]);
                    float v0 = ac[nt * 4 + jo + 0] + dist * wds[c] + be1s[c] + a2.x + b2.x;
                    float v1 = ac[nt * 4 + jo + 1] + dist * wds[c + 1] + be1s[c + 1] +
                               a2.y + b2.y;
                    tileh[row * SPH + hslot(c >> 1)] = pack_h2(siluf(v0), siluf(v1));
                }
            }
        }
        __syncthreads();  // A

        // ---- GEMM1 (fp16): mm = s @ We2 + be2 ----
        float accmA[4][4], accmB[4][4];
#pragma unroll
        for (int nt = 0; nt < 4; nt++) {
            int cb = ncol + nt * 8 + tg * 2;
            float b0v = be2s[cb], b1v = be2s[cb + 1];
            accmA[nt][0] = b0v; accmA[nt][1] = b1v;
            accmA[nt][2] = b0v; accmA[nt][3] = b1v;
            accmB[nt][0] = b0v; accmB[nt][1] = b1v;
            accmB[nt][2] = b0v; accmB[nt][3] = b1v;
        }
        gemm_kloop32h(tileh, wt2h, mrow, ncol, lane, accmA, accmB);

        // agg scatter: pair-merge via shfl -> red.v4 (half the ops)
#pragma unroll
        for (int rr = 0; rr < 4; rr++) {
            int row = mrow + g + rr * 8;
            const float* ac = (rr < 2) ? &accmA[0][0] : &accmB[0][0];
            int jo = (rr & 1) * 2;
            int di = ((const int*)sEA)[row * 20 + 18];
#pragma unroll
            for (int nt = 0; nt < 4; nt++) {
                float v0 = ac[nt * 4 + jo + 0];
                float v1 = ac[nt * 4 + jo + 1];
                float o0 = __shfl_xor_sync(0xffffffffu, v0, 1);
                float o1 = __shfl_xor_sync(0xffffffffu, v1, 1);
                if ((tg & 1) == 0) {
                    int c = ncol + nt * 8 + tg * 2;
                    asm volatile("red.global.add.v4.f32 [%0], {%1,%2,%3,%4};"
                                 :: "l"(&g_agg[di * 128 + c]),
                                    "f"(v0), "f"(v1), "f"(o0), "f"(o1)
                                 : "memory");
                }
            }
        }
        __syncthreads();  // B (all warps done reading s before overwrite)

        // store mm into tileh (fp16 perm)
#pragma unroll
        for (int rr = 0; rr < 4; rr++) {
            int row = mrow + g + rr * 8;
            const float* ac = (rr < 2) ? &accmA[0][0] : &accmB[0][0];
            int jo = (rr & 1) * 2;
#pragma unroll
            for (int nt = 0; nt < 4; nt++) {
                int c = ncol + nt * 8 + tg * 2;
                tileh[row * SPH + hslot(c >> 1)] =
                    pack_h2(ac[nt * 4 + jo + 0], ac[nt * 4 + jo + 1]);
            }
        }
        __syncthreads();  // C

        // ---- prefetch next tile (regs) + snapshot scatter info ----
        float4 pea;
        int psi = 0, pdi = 0;
        float pdx = 0.f, pdy = 0.f, pdz = 0.f;
        if (hn) {
            int e = tn * 128 + e_l;
            pea = *(const float4*)&ea[e * 16 + q * 4];
            if (q == 0) {
                psi = g_src[e];
                pdi = g_dst[e];
                pdx = x[pdi * 3 + 0] - x[psi * 3 + 0];
                pdy = x[pdi * 3 + 1] - x[psi * 3 + 1];
                pdz = x[pdi * 3 + 2] - x[psi * 3 + 2];
            }
        }
        int xsi = 0, xdi = 0;
        if (tid < 128) {
            xsi = ((const int*)sEA)[tid * 20 + 17];
            xdi = ((const int*)sEA)[tid * 20 + 18];
        }

        // ---- GEMM2 (fp16): gate = sum silu(mm@Wx1+bx1)*wx2 ----
        {
            float accA[4][4], accB[4][4];
#pragma unroll
            for (int nt = 0; nt < 4; nt++) {
                int cb = ncol + nt * 8 + tg * 2;
                float b0v = bx1s[cb], b1v = bx1s[cb + 1];
                accA[nt][0] = b0v; accA[nt][1] = b1v;
                accA[nt][2] = b0v; accA[nt][3] = b1v;
                accB[nt][0] = b0v; accB[nt][1] = b1v;
                accB[nt][2] = b0v; accB[nt][3] = b1v;
            }
            gemm_kloop32h(tileh, wtxh, mrow, ncol, lane, accA, accB);
            float p[4] = {0.f, 0.f, 0.f, 0.f};
#pragma unroll
            for (int nt = 0; nt < 4; nt++) {
                int cb = ncol + nt * 8 + tg * 2;
                float w0 = wx2s[cb], w1 = wx2s[cb + 1];
                p[0] += siluf(accA[nt][0]) * w0 + siluf(accA[nt][1]) * w1;
                p[1] += siluf(accA[nt][2]) * w0 + siluf(accA[nt][3]) * w1;
                p[2] += siluf(accB[nt][0]) * w0 + siluf(accB[nt][1]) * w1;
                p[3] += siluf(accB[nt][2]) * w0 + siluf(accB[nt][3]) * w1;
            }
#pragma unroll
            for (int i = 0; i < 4; i++) {
                p[i] += __shfl_xor_sync(0xffffffffu, p[i], 1);
                p[i] += __shfl_xor_sync(0xffffffffu, p[i], 2);
            }
            if (tg == 0) {
                atomicAdd(&sg_cur[mrow + g], p[0]);
                atomicAdd(&sg_cur[mrow + g + 8], p[1]);
                atomicAdd(&sg_cur[mrow + g + 16], p[2]);
                atomicAdd(&sg_cur[mrow + g + 24], p[3]);
            }
        }
        __syncthreads();  // D

        // ---- x scatter (snapshotted indices) + stage next tile ----
        if (tid < 128) {
            float dx = x[xdi * 3 + 0] - x[xsi * 3 + 0];
            float dy = x[xdi * 3 + 1] - x[xsi * 3 + 1];
            float dz = x[xdi * 3 + 2] - x[xsi * 3 + 2];
            float rn = __fdividef(1.0f, sqrtf(dx * dx + dy * dy + dz * dz) + 1e-9f);
            float gte = sg_cur[tid];
            atomicAdd(&outx[xdi * 3 + 0], dx * rn * gte);
            atomicAdd(&outx[xdi * 3 + 1], dy * rn * gte);
            atomicAdd(&outx[xdi * 3 + 2], dz * rn * gte);
            sg_nxt[tid] = bx2v;
        }
        if (hn) {
            *(float4*)&sEA[e_l * 20 + q * 4] = pea;
            if (q == 0) {
                sEA[e_l * 20 + 16] = sqrtf(pdx * pdx + pdy * pdy + pdz * pdz + 1e-9f);
                ((int*)sEA)[e_l * 20 + 17] = psi;
                ((int*)sEA)[e_l * 20 + 18] = pdi;
            }
        }
        __syncthreads();  // E
        pb ^= 1;
    }
}

// ---------------- node update (persistent, 1024 thr, tf32) ------------------
__global__ __launch_bounds__(1024, 1) void k_node_upd(
    const float* __restrict__ h, const float* __restrict__ Wh1,
    const float* __restrict__ bh1, const float* __restrict__ Wh2,
    const float* __restrict__ bh2, const float* __restrict__ lng,
    const float* __restrict__ lnb, float* __restrict__ outh) {
    extern __shared__ float sm[];
    float* hr = sm;              // 128*SP fp32 row-major
    float* ap = hr + 128 * SP;   // 128*SP perm tf32 (agg, then tt)
    float* wt = ap + 128 * SP;
    float* bh1s = wt + 128 * SP;
    float* bh2s = bh1s + 128;
    float* lngs = bh2s + 128;
    float* lnbs = lngs + 128;
    float* ssum = lnbs + 128;
    float* ssq = ssum + 128;

    int tid = threadIdx.x, lane = tid & 31, warp = tid >> 5;
    if (tid < 128) {
        bh1s[tid] = bh1[tid];
        bh2s[tid] = bh2[tid];
        lngs[tid] = lng[tid];
        lnbs[tid] = lnb[tid];
    }

    int mrow = (warp >> 2) * 16, ncol = (warp & 3) * 32;
    int g = lane >> 2, tg = lane & 3;

    for (int t = blockIdx.x; t < NTILE_N; t += gridDim.x) {
        int n0 = t * 128;
        if (tid < 128) {
            ssum[tid] = 0.f;
            ssq[tid] = 0.f;
        }
#pragma unroll
        for (int v = 0; v < 4; v++) {
            int f = v * 1024 + tid;
            int r = f >> 5, c4 = (f & 31) * 4;
            float4 hv = make_float4(0.f, 0.f, 0.f, 0.f);
            float4 av = make_float4(0.f, 0.f, 0.f, 0.f);
            if (n0 + r < NN) {
                hv = *(const float4*)&h[(n0 + r) * 128 + c4];
                av = *(const float4*)&g_agg[(n0 + r) * 128 + c4];
            }
            *(float4*)&hr[r * SP + c4] = hv;
            int base = r * SP + (c4 & ~7);
            int off = (c4 & 7) >> 2;
            ap[base + 0 + off] = __uint_as_float(f2tf(av.x));
            ap[base + 2 + off] = __uint_as_float(f2tf(av.y));
            ap[base + 4 + off] = __uint_as_float(f2tf(av.z));
            ap[base + 6 + off] = __uint_as_float(f2tf(av.w));
        }
        stage_wtn1024(wt, Wh1, tid);
        __syncthreads();

        float acc[4][4];
#pragma unroll
        for (int nt = 0; nt < 4; nt++) {
            int cb = ncol + nt * 8 + tg * 2;
            float b0v = bh1s[cb], b1v = bh1s[cb + 1];
            acc[nt][0] = b0v; acc[nt][1] = b1v;
            acc[nt][2] = b0v; acc[nt][3] = b1v;
        }
        gemm_kloop16n(hr, wt, mrow, ncol, lane, acc);
        __syncthreads();
        stage_wtp1024(wt, Wh1 + 128 * 128, tid);
        __syncthreads();
        gemm_kloop16p(ap, wt, mrow, ncol, lane, acc);
        __syncthreads();

#pragma unroll
        for (int rr = 0; rr < 2; rr++) {
            int row = mrow + g + rr * 8;
#pragma unroll
            for (int nt = 0; nt < 4; nt++) {
                int c = ncol + nt * 8 + tg * 2;
                int base = row * SP + (c & ~7);
                int j = c & 7;
                ap[base + (j & 3) * 2 + (j >> 2)] =
                    __uint_as_float(f2tf(siluf(acc[nt][rr * 2 + 0])));
                ap[base + ((j + 1) & 3) * 2 + ((j + 1) >> 2)] =
                    __uint_as_float(f2tf(siluf(acc[nt][rr * 2 + 1])));
            }
        }
        stage_wtp1024(wt, Wh2, tid);
        __syncthreads();

        float acc2[4][4];
#pragma unroll
        for (int nt = 0; nt < 4; nt++) {
            int cb = ncol + nt * 8 + tg * 2;
            float b0v = bh2s[cb], b1v = bh2s[cb + 1];
            acc2[nt][0] = b0v; acc2[nt][1] = b1v;
            acc2[nt][2] = b0v; acc2[nt][3] = b1v;
        }
        gemm_kloop16p(ap, wt, mrow, ncol, lane, acc2);

        float vsum[2] = {0.f, 0.f}, vsq[2] = {0.f, 0.f};
#pragma unroll
        for (int rr = 0; rr < 2; rr++) {
            int row = mrow + g + rr * 8;
#pragma unroll
            for (int nt = 0; nt < 4; nt++) {
                int cb = ncol + nt * 8 + tg * 2;
                float v0 = hr[row * SP + cb] + acc2[nt][rr * 2 + 0];
                float v1 = hr[row * SP + cb + 1] + acc2[nt][rr * 2 + 1];
                acc2[nt][rr * 2 + 0] = v0;
                acc2[nt][rr * 2 + 1] = v1;
                vsum[rr] += v0 + v1;
                vsq[rr] += v0 * v0 + v1 * v1;
            }
        }
#pragma unroll
        for (int i = 0; i < 2; i++) {
            vsum[i] += __shfl_xor_sync(0xffffffffu, vsum[i], 1);
            vsum[i] += __shfl_xor_sync(0xffffffffu, vsum[i], 2);
            vsq[i] += __shfl_xor_sync(0xffffffffu, vsq[i], 1);
            vsq[i] += __shfl_xor_sync(0xffffffffu, vsq[i], 2);
        }
        if (tg == 0) {
            atomicAdd(&ssum[mrow + g], vsum[0]);
            atomicAdd(&ssq[mrow + g], vsq[0]);
            atomicAdd(&ssum[mrow + g + 8], vsum[1]);
            atomicAdd(&ssq[mrow + g + 8], vsq[1]);
        }
        __syncthreads();

#pragma unroll
        for (int rr = 0; rr < 2; rr++) {
            int row = mrow + g + rr * 8;
            float mean = ssum[row] * (1.0f / 128.0f);
            float var = ssq[row] * (1.0f / 128.0f) - mean * mean;
            float rstd = rsqrtf(var + 1e-5f);
            if (n0 + row < NN) {
#pragma unroll
                for (int nt = 0; nt < 4; nt++) {
                    int cb = ncol + nt * 8 + tg * 2;
                    *(float2*)&outh[(n0 + row) * 128 + cb] = make_float2(
                        (acc2[nt][rr * 2 + 0] - mean) * rstd * lngs[cb] + lnbs[cb],
                        (acc2[nt][rr * 2 + 1] - mean) * rstd * lngs[cb + 1] + lnbs[cb + 1]);
                }
            }
        }
        __syncthreads();
    }
}

// ---------------- launcher ---------------------------------------------------
extern "C" void kernel_launch(void* const* d_in, const int* in_sizes, int n_in,
                              void* d_out, int out_size) {
    const float* h = (const float*)d_in[0];
    const float* x = (const float*)d_in[1];
    const void* ei = d_in[2];
    const float* ea = (const float*)d_in[3];
    const float* We1 = (const float*)d_in[4];
    const float* be1 = (const float*)d_in[5];
    const float* We2 = (const float*)d_in[6];
    const float* be2 = (const float*)d_in[7];
    const float* Wh1 = (const float*)d_in[8];
    const float* bh1 = (const float*)d_in[9];
    const float* Wh2 = (const float*)d_in[10];
    const float* bh2 = (const float*)d_in[11];
    const float* Wx1 = (const float*)d_in[12];
    const float* bx1 = (const float*)d_in[13];
    const float* Wx2 = (const float*)d_in[14];
    const float* bx2 = (const float*)d_in[15];
    const float* lng = (const float*)d_in[16];
    const float* lnb = (const float*)d_in[17];

    float* outh = (float*)d_out;
    float* outx = outh + (size_t)NN * 128;

    const int SMEM_EDGE = (3 * 128 * SPH + 128 * 20 + 128 * 16 + 5 * 128 + 256) * 4;  // 132608
    const int SMEM_PRE = (3 * 128 * SP) * 4;                                           // 208896
    const int SMEM_UPD = (3 * 128 * SP + 6 * 128) * 4;                                 // 211968
    cudaFuncSetAttribute(k_edge, cudaFuncAttributeMaxDynamicSharedMemorySize, SMEM_EDGE);
    cudaFuncSetAttribute(k_node_pre, cudaFuncAttributeMaxDynamicSharedMemorySize, SMEM_PRE);
    cudaFuncSetAttribute(k_node_upd, cudaFuncAttributeMaxDynamicSharedMemorySize, SMEM_UPD);

    k_detect<<<1, 32>>>(ei);
    k_convert<<<(EE + 255) / 256, 256>>>(ei);
    k_init<<<1024, 256>>>(x, outx);
    k_node_pre<<<PGRID, 1024, SMEM_PRE>>>(h, We1);
    k_edge<<<PGRID, 512, SMEM_EDGE>>>(x, ea, We1, be1, We2, be2, Wx1, bx1, Wx2,
                                      bx2, outx);
    k_node_upd<<<PGRID, 1024, SMEM_UPD>>>(h, Wh1, bh1, Wh2, bh2, lng, lnb, outh);
}